// round 2
// baseline (speedup 1.0000x reference)
#include <cuda_runtime.h>
#include <math.h>

#define BB 2
#define TT 2048
#define EE 1024
#define HH 16
#define DD 64
#define BT (BB*TT)            // 4096
#define BIAS_LEN (2*TT-1)     // 4095

// Scratch (device globals: no allocations allowed)
__device__ float g_q[BB*HH*TT*DD];
__device__ float g_k[BB*HH*TT*DD];
__device__ float g_v[BB*HH*TT*DD];
__device__ float g_ctx[BB*TT*EE];
__device__ float g_gate[BB*HH*TT];
__device__ float g_bias[BIAS_LEN*HH];

// ---------------------------------------------------------------------------
// Position-bias table: bias depends only on delta = s - t. 4095 x H entries.
// ---------------------------------------------------------------------------
__global__ void bias_table_kernel(const float* __restrict__ rel_embed)
{
    int idx = blockIdx.x * blockDim.x + threadIdx.x;
    if (idx >= BIAS_LEN) return;
    int delta = idx - (TT - 1);
    const int nb = 160;          // NUM_BUCKETS/2
    const int max_exact = 80;    // nb/2
    int rb = (delta > 0) ? nb : 0;
    int rel = abs(delta);
    int v;
    if (rel < max_exact) {
        v = rel;
    } else {
        float rf = (float)(rel < 1 ? 1 : rel);
        // log(rel/80)/log(800/80)*(160-80)
        float large = logf(rf * (1.0f/80.0f)) * (float)(80.0 / 2.302585092994045684);
        int li = (int)((float)max_exact + large);   // truncation like .astype(int32)
        v = li < (nb - 1) ? li : (nb - 1);
    }
    int bucket = rb + v;
    #pragma unroll
    for (int h = 0; h < HH; h++)
        g_bias[idx*HH + h] = rel_embed[bucket*HH + h];
}

// ---------------------------------------------------------------------------
// Gate: gate_out[b,h,t] = ga*(gb*gru_const[h]-1)+2 from 8 dot-products over D
// ---------------------------------------------------------------------------
__global__ void gate_kernel(const float* __restrict__ hidden,
                            const float* __restrict__ gru_w,
                            const float* __restrict__ gru_b,
                            const float* __restrict__ gru_const)
{
    __shared__ float sw[8*DD];
    __shared__ float sb[8];
    __shared__ float sc[HH];
    int tid = threadIdx.x;
    // NOTE: 8*DD = 512 > blockDim (256) -> strided loop, NOT a single guarded store.
    for (int i = tid; i < 8*DD; i += blockDim.x) sw[i] = gru_w[i];
    if (tid < 8)    sb[tid] = gru_b[tid];
    if (tid < HH)   sc[tid] = gru_const[tid];
    __syncthreads();

    int i = blockIdx.x * blockDim.x + tid;
    if (i >= BB*TT*HH) return;
    int h  = i % HH;
    int bt = i / HH;
    const float* x = hidden + (size_t)bt*EE + h*DD;

    float p[8];
    #pragma unroll
    for (int j = 0; j < 8; j++) p[j] = sb[j];
    #pragma unroll
    for (int d = 0; d < DD; d += 4) {
        float4 xv = *(const float4*)&x[d];
        #pragma unroll
        for (int j = 0; j < 8; j++) {
            p[j] += xv.x*sw[j*DD+d] + xv.y*sw[j*DD+d+1]
                  + xv.z*sw[j*DD+d+2] + xv.w*sw[j*DD+d+3];
        }
    }
    float pa = p[0]+p[1]+p[2]+p[3];
    float pb = p[4]+p[5]+p[6]+p[7];
    float ga = 1.0f/(1.0f + __expf(-pa));
    float gb = 1.0f/(1.0f + __expf(-pb));
    float gout = ga*(gb*sc[h] - 1.0f) + 2.0f;
    int b = bt / TT, t = bt % TT;
    g_gate[(b*HH + h)*TT + t] = gout;
}

// ---------------------------------------------------------------------------
// Shared 128x128x8 fp32 GEMM tile: acc[i][j] = sum_k A[m,k]*W[n,k]
// (y = x @ W^T). 256 threads, 8x8 per thread.
// ---------------------------------------------------------------------------
__device__ __forceinline__ void sgemm_128x128(const float* __restrict__ A,
                                              const float* __restrict__ W,
                                              int m0, int n0,
                                              float acc[8][8])
{
    __shared__ float As[8][128];
    __shared__ float Bs[8][132];
    int tid = threadIdx.x;
    int tx = tid & 15, ty = tid >> 4;
    int lrow = tid >> 1;           // 0..127
    int lk   = (tid & 1) * 4;      // 0 or 4
    const float* aptr = A + (size_t)(m0 + lrow)*EE + lk;
    const float* bptr = W + (size_t)(n0 + lrow)*EE + lk;

    for (int k0 = 0; k0 < EE; k0 += 8) {
        float4 av = *(const float4*)(aptr + k0);
        float4 bv = *(const float4*)(bptr + k0);
        __syncthreads();
        As[lk+0][lrow] = av.x; As[lk+1][lrow] = av.y;
        As[lk+2][lrow] = av.z; As[lk+3][lrow] = av.w;
        Bs[lk+0][lrow] = bv.x; Bs[lk+1][lrow] = bv.y;
        Bs[lk+2][lrow] = bv.z; Bs[lk+3][lrow] = bv.w;
        __syncthreads();
        #pragma unroll
        for (int kk = 0; kk < 8; kk++) {
            float a[8], b[8];
            #pragma unroll
            for (int i = 0; i < 8; i++) a[i] = As[kk][ty*8 + i];
            #pragma unroll
            for (int j = 0; j < 8; j++) b[j] = Bs[kk][tx*8 + j];
            #pragma unroll
            for (int i = 0; i < 8; i++)
                #pragma unroll
                for (int j = 0; j < 8; j++)
                    acc[i][j] += a[i]*b[j];
        }
    }
}

// ---------------------------------------------------------------------------
// QKV projections (grid.z selects matrix), writes (B,H,T,D); q scaled.
// ---------------------------------------------------------------------------
__global__ __launch_bounds__(256) void qkv_gemm_kernel(
    const float* __restrict__ x,
    const float* __restrict__ qw, const float* __restrict__ qb,
    const float* __restrict__ kw, const float* __restrict__ kb,
    const float* __restrict__ vw, const float* __restrict__ vb)
{
    const float* W; const float* bias; float* dst; float scale;
    if (blockIdx.z == 0)      { W = qw; bias = qb; dst = g_q; scale = 0.125f; }
    else if (blockIdx.z == 1) { W = kw; bias = kb; dst = g_k; scale = 1.0f; }
    else                      { W = vw; bias = vb; dst = g_v; scale = 1.0f; }

    int m0 = blockIdx.y * 128, n0 = blockIdx.x * 128;
    float acc[8][8] = {};
    sgemm_128x128(x, W, m0, n0, acc);

    int tx = threadIdx.x & 15, ty = threadIdx.x >> 4;
    #pragma unroll
    for (int i = 0; i < 8; i++) {
        int m = m0 + ty*8 + i;
        int b = m >> 11;           // m / T
        int t = m & (TT - 1);
        #pragma unroll
        for (int j = 0; j < 8; j++) {
            int n = n0 + tx*8 + j;
            int h = n >> 6, d = n & 63;
            float v = (acc[i][j] + bias[n]) * scale;
            dst[(((size_t)(b*HH + h))*TT + t)*DD + d] = v;
        }
    }
}

// ---------------------------------------------------------------------------
// Output projection: out = ctx @ out_w^T + out_b
// ---------------------------------------------------------------------------
__global__ __launch_bounds__(256) void out_gemm_kernel(
    const float* __restrict__ ow, const float* __restrict__ ob,
    float* __restrict__ out)
{
    int m0 = blockIdx.y * 128, n0 = blockIdx.x * 128;
    float acc[8][8] = {};
    sgemm_128x128(g_ctx, ow, m0, n0, acc);

    int tx = threadIdx.x & 15, ty = threadIdx.x >> 4;
    #pragma unroll
    for (int i = 0; i < 8; i++) {
        int m = m0 + ty*8 + i;
        #pragma unroll
        for (int j = 0; j < 8; j++) {
            int n = n0 + tx*8 + j;
            out[(size_t)m*EE + n] = acc[i][j] + ob[n];
        }
    }
}

// ---------------------------------------------------------------------------
// Flash attention, fp32, 64x64 tiles. Block = (b,h) x 64 q-rows. 256 threads.
// ---------------------------------------------------------------------------
#define PITCH 68
#define ATTN_SMEM ((4*64*PITCH + 128 + 64) * (int)sizeof(float))

__global__ __launch_bounds__(256) void attn_kernel()
{
    extern __shared__ float sm[];
    float* Qs     = sm;                    // [row][d]   64 x PITCH
    float* Kst    = Qs  + 64*PITCH;        // [d][s]     64 x PITCH (transposed)
    float* Vs     = Kst + 64*PITCH;        // [s][d]     64 x PITCH
    float* Ps     = Vs  + 64*PITCH;        // [row][s]   64 x PITCH
    float* bias_s = Ps  + 64*PITCH;        // 128
    float* gate_s = bias_s + 128;          // 64

    int tid = threadIdx.x;
    int tx = tid & 15, ty = tid >> 4;
    int bh = blockIdx.y;                   // b*H + h
    int b = bh >> 4, h = bh & 15;
    int t0 = blockIdx.x * 64;

    const float* qbase = g_q + ((size_t)bh*TT + t0)*DD;
    const float* kbase = g_k + (size_t)bh*TT*DD;
    const float* vbase = g_v + (size_t)bh*TT*DD;

    // Load Q tile
    {
        int r = tid >> 4;
        int c = (tid & 15) * 4;
        #pragma unroll
        for (int it = 0; it < 4; it++) {
            int row = it*16 + r;
            float4 v = *(const float4*)&qbase[(size_t)row*DD + c];
            float* p = &Qs[row*PITCH + c];
            p[0] = v.x; p[1] = v.y; p[2] = v.z; p[3] = v.w;
        }
    }
    if (tid < 64) gate_s[tid] = g_gate[(size_t)bh*TT + t0 + tid];

    float m_run[4], l_run[4];
    #pragma unroll
    for (int ri = 0; ri < 4; ri++) { m_run[ri] = -1e30f; l_run[ri] = 0.0f; }
    float oacc[4][4] = {};

    for (int s0 = 0; s0 < TT; s0 += 64) {
        __syncthreads();   // previous PV reads of Vs/Ps done; Qs/gate ready (1st iter)
        // Load K (transposed) and V tiles
        {
            int r = tid >> 4;
            int c = (tid & 15) * 4;
            #pragma unroll
            for (int it = 0; it < 4; it++) {
                int row = it*16 + r;
                float4 kv = *(const float4*)&kbase[(size_t)(s0+row)*DD + c];
                Kst[(c+0)*PITCH + row] = kv.x;
                Kst[(c+1)*PITCH + row] = kv.y;
                Kst[(c+2)*PITCH + row] = kv.z;
                Kst[(c+3)*PITCH + row] = kv.w;
                float4 vv = *(const float4*)&vbase[(size_t)(s0+row)*DD + c];
                float* p = &Vs[row*PITCH + c];
                p[0] = vv.x; p[1] = vv.y; p[2] = vv.z; p[3] = vv.w;
            }
        }
        // Bias window: bias_s[j - i + 63], delta = (s0+j)-(t0+i)
        if (tid < 128) {
            int gidx = s0 - t0 + tid - 63 + (TT - 1);
            bias_s[tid] = (gidx >= 0 && gidx < BIAS_LEN) ? g_bias[gidx*HH + h] : 0.0f;
        }
        __syncthreads();

        // S = Q K^T (4x4 per thread)
        float s[4][4] = {};
        #pragma unroll
        for (int d0 = 0; d0 < DD; d0 += 4) {
            float4 q4[4];
            #pragma unroll
            for (int ri = 0; ri < 4; ri++)
                q4[ri] = *(const float4*)&Qs[(ty*4+ri)*PITCH + d0];
            #pragma unroll
            for (int dd = 0; dd < 4; dd++) {
                float4 k4 = *(const float4*)&Kst[(d0+dd)*PITCH + tx*4];
                #pragma unroll
                for (int ri = 0; ri < 4; ri++) {
                    float qv = dd==0 ? q4[ri].x : dd==1 ? q4[ri].y : dd==2 ? q4[ri].z : q4[ri].w;
                    s[ri][0] += qv*k4.x; s[ri][1] += qv*k4.y;
                    s[ri][2] += qv*k4.z; s[ri][3] += qv*k4.w;
                }
            }
        }

        // Bias + online softmax (row stats kept redundantly across 16 tx lanes)
        #pragma unroll
        for (int ri = 0; ri < 4; ri++) {
            int row = ty*4 + ri;
            float g = gate_s[row];
            float rmax = -1e30f;
            #pragma unroll
            for (int cj = 0; cj < 4; cj++) {
                int j = tx*4 + cj;
                float val = s[ri][cj] + g * bias_s[j - row + 63];
                s[ri][cj] = val;
                rmax = fmaxf(rmax, val);
            }
            #pragma unroll
            for (int off = 8; off >= 1; off >>= 1)
                rmax = fmaxf(rmax, __shfl_xor_sync(0xffffffffu, rmax, off));
            float m_new = fmaxf(m_run[ri], rmax);
            float alpha = __expf(m_run[ri] - m_new);
            float rsum = 0.0f;
            float pv0, pv1, pv2, pv3;
            pv0 = __expf(s[ri][0] - m_new); rsum += pv0;
            pv1 = __expf(s[ri][1] - m_new); rsum += pv1;
            pv2 = __expf(s[ri][2] - m_new); rsum += pv2;
            pv3 = __expf(s[ri][3] - m_new); rsum += pv3;
            #pragma unroll
            for (int off = 8; off >= 1; off >>= 1)
                rsum += __shfl_xor_sync(0xffffffffu, rsum, off);
            l_run[ri] = l_run[ri]*alpha + rsum;
            m_run[ri] = m_new;
            #pragma unroll
            for (int ci = 0; ci < 4; ci++) oacc[ri][ci] *= alpha;
            float4 pq = make_float4(pv0, pv1, pv2, pv3);
            *(float4*)&Ps[row*PITCH + tx*4] = pq;
        }
        __syncthreads();

        // O += P @ V
        #pragma unroll
        for (int j0 = 0; j0 < 64; j0 += 4) {
            float4 p4[4];
            #pragma unroll
            for (int ri = 0; ri < 4; ri++)
                p4[ri] = *(const float4*)&Ps[(ty*4+ri)*PITCH + j0];
            #pragma unroll
            for (int jj = 0; jj < 4; jj++) {
                float4 v4 = *(const float4*)&Vs[(j0+jj)*PITCH + tx*4];
                #pragma unroll
                for (int ri = 0; ri < 4; ri++) {
                    float pv = jj==0 ? p4[ri].x : jj==1 ? p4[ri].y : jj==2 ? p4[ri].z : p4[ri].w;
                    oacc[ri][0] += pv*v4.x; oacc[ri][1] += pv*v4.y;
                    oacc[ri][2] += pv*v4.z; oacc[ri][3] += pv*v4.w;
                }
            }
        }
    }

    // Finalize: divide by l, write ctx in (B,T,E) layout
    #pragma unroll
    for (int ri = 0; ri < 4; ri++) {
        int t = t0 + ty*4 + ri;
        float inv = 1.0f / l_run[ri];
        float4 o = make_float4(oacc[ri][0]*inv, oacc[ri][1]*inv,
                               oacc[ri][2]*inv, oacc[ri][3]*inv);
        *(float4*)&g_ctx[((size_t)b*TT + t)*EE + h*DD + tx*4] = o;
    }
}

// ---------------------------------------------------------------------------
extern "C" void kernel_launch(void* const* d_in, const int* in_sizes, int n_in,
                              void* d_out, int out_size)
{
    const float* hidden    = (const float*)d_in[0];
    const float* q_w       = (const float*)d_in[1];
    const float* q_b       = (const float*)d_in[2];
    const float* k_w       = (const float*)d_in[3];
    const float* k_b       = (const float*)d_in[4];
    const float* v_w       = (const float*)d_in[5];
    const float* v_b       = (const float*)d_in[6];
    const float* out_w     = (const float*)d_in[7];
    const float* out_b     = (const float*)d_in[8];
    const float* rel_embed = (const float*)d_in[9];
    const float* gru_const = (const float*)d_in[10];
    const float* gru_w     = (const float*)d_in[11];
    const float* gru_b     = (const float*)d_in[12];
    float* out = (float*)d_out;

    bias_table_kernel<<<(BIAS_LEN + 255)/256, 256>>>(rel_embed);
    gate_kernel<<<(BB*TT*HH + 255)/256, 256>>>(hidden, gru_w, gru_b, gru_const);

    dim3 gq(EE/128, BT/128, 3);
    qkv_gemm_kernel<<<gq, 256>>>(hidden, q_w, q_b, k_w, k_b, v_w, v_b);

    cudaFuncSetAttribute(attn_kernel, cudaFuncAttributeMaxDynamicSharedMemorySize, ATTN_SMEM);
    attn_kernel<<<dim3(TT/64, BB*HH), 256, ATTN_SMEM>>>();

    out_gemm_kernel<<<dim3(EE/128, BT/128), 256>>>(out_w, out_b, out);
}

// round 4
// speedup vs baseline: 1.3946x; 1.3946x over previous
#include <cuda_runtime.h>
#include <cuda_bf16.h>
#include <math.h>
#include <stdint.h>

#define BB 2
#define TT 2048
#define EE 1024
#define HH 16
#define DD 64
#define BT (BB*TT)            // 4096
#define BIAS_LEN (2*TT-1)     // 4095

// Scratch (device globals: no allocations allowed)
__device__ float g_q[BB*HH*TT*DD];
__device__ float g_k[BB*HH*TT*DD];
__device__ float g_v[BB*HH*TT*DD];
__device__ float g_ctx[BB*TT*EE];
__device__ float g_gate[BB*HH*TT];
__device__ float g_bias[BIAS_LEN*HH];
// bf16 hi/lo split operands for tensor-core GEMMs
__device__ __nv_bfloat16 g_xhi[BT*EE], g_xlo[BT*EE];        // hidden
__device__ __nv_bfloat16 g_whi[4*EE*EE], g_wlo[4*EE*EE];    // q,k,v,out weights
__device__ __nv_bfloat16 g_chi[BT*EE], g_clo[BT*EE];        // ctx

// ===========================================================================
// fp32 -> bf16 hi/lo conversions
// ===========================================================================
__global__ void conv_x_kernel(const float* __restrict__ src)
{
    int i = (blockIdx.x * blockDim.x + threadIdx.x) * 4;
    if (i >= BT*EE) return;
    float4 v = *(const float4*)&src[i];
    __nv_bfloat16 h0 = __float2bfloat16(v.x), h1 = __float2bfloat16(v.y);
    __nv_bfloat16 h2 = __float2bfloat16(v.z), h3 = __float2bfloat16(v.w);
    __nv_bfloat162 hp[2] = {{h0,h1},{h2,h3}};
    *(uint2*)&g_xhi[i] = *(uint2*)hp;
    __nv_bfloat162 lp[2] = {
        {__float2bfloat16(v.x - __bfloat162float(h0)), __float2bfloat16(v.y - __bfloat162float(h1))},
        {__float2bfloat16(v.z - __bfloat162float(h2)), __float2bfloat16(v.w - __bfloat162float(h3))}};
    *(uint2*)&g_xlo[i] = *(uint2*)lp;
}
__global__ void conv_w_kernel(const float* __restrict__ w0, const float* __restrict__ w1,
                              const float* __restrict__ w2, const float* __restrict__ w3)
{
    int i = (blockIdx.x * blockDim.x + threadIdx.x) * 4;
    if (i >= 4*EE*EE) return;
    int sel = i >> 20;
    const float* src = sel==0 ? w0 : sel==1 ? w1 : sel==2 ? w2 : w3;
    float4 v = *(const float4*)&src[i & ((1<<20)-1)];
    __nv_bfloat16 h0 = __float2bfloat16(v.x), h1 = __float2bfloat16(v.y);
    __nv_bfloat16 h2 = __float2bfloat16(v.z), h3 = __float2bfloat16(v.w);
    __nv_bfloat162 hp[2] = {{h0,h1},{h2,h3}};
    *(uint2*)&g_whi[i] = *(uint2*)hp;
    __nv_bfloat162 lp[2] = {
        {__float2bfloat16(v.x - __bfloat162float(h0)), __float2bfloat16(v.y - __bfloat162float(h1))},
        {__float2bfloat16(v.z - __bfloat162float(h2)), __float2bfloat16(v.w - __bfloat162float(h3))}};
    *(uint2*)&g_wlo[i] = *(uint2*)lp;
}
__global__ void conv_c_kernel()
{
    int i = (blockIdx.x * blockDim.x + threadIdx.x) * 4;
    if (i >= BT*EE) return;
    float4 v = *(const float4*)&g_ctx[i];
    __nv_bfloat16 h0 = __float2bfloat16(v.x), h1 = __float2bfloat16(v.y);
    __nv_bfloat16 h2 = __float2bfloat16(v.z), h3 = __float2bfloat16(v.w);
    __nv_bfloat162 hp[2] = {{h0,h1},{h2,h3}};
    *(uint2*)&g_chi[i] = *(uint2*)hp;
    __nv_bfloat162 lp[2] = {
        {__float2bfloat16(v.x - __bfloat162float(h0)), __float2bfloat16(v.y - __bfloat162float(h1))},
        {__float2bfloat16(v.z - __bfloat162float(h2)), __float2bfloat16(v.w - __bfloat162float(h3))}};
    *(uint2*)&g_clo[i] = *(uint2*)lp;
}

// ===========================================================================
// mma.sync m16n8k16 bf16 helper: C(f32) += A(bf16) * B(bf16)
// A row-major fragment, B col-major fragment (k-contiguous in both sources).
// ===========================================================================
__device__ __forceinline__ void hmma16816(float c[4],
                                          uint32_t a0, uint32_t a1, uint32_t a2, uint32_t a3,
                                          uint32_t b0, uint32_t b1)
{
    asm volatile(
        "mma.sync.aligned.m16n8k16.row.col.f32.bf16.bf16.f32 "
        "{%0,%1,%2,%3}, {%4,%5,%6,%7}, {%8,%9}, {%0,%1,%2,%3};"
        : "+f"(c[0]), "+f"(c[1]), "+f"(c[2]), "+f"(c[3])
        : "r"(a0), "r"(a1), "r"(a2), "r"(a3), "r"(b0), "r"(b1));
}

// ===========================================================================
// HMMA GEMM: Y[m,n] = sum_k A[m,k]*W[n,k] (+bias), bf16 hi/lo 3-pass.
// Block tile 128x128, K-chunks of 64 in smem. 8 warps as 2(m) x 4(n),
// warp tile 64x32 = 4 m-frags x 4 n-frags.
// sel 0/1/2: qkv epilogue ((B,H,T,D) + scale). sel 3: dense out.
// ===========================================================================
#define KC 64
#define SPITCH 72                      // bf16 elems per smem row (conflict-free)
#define SM_A_HI 0
#define SM_A_LO (128*SPITCH)
#define SM_B_HI (2*128*SPITCH)
#define SM_B_LO (3*128*SPITCH)
#define GEMM_SMEM (4*128*SPITCH*2)     // bytes (bf16)

__global__ __launch_bounds__(256) void hmma_gemm_kernel(
    const float* __restrict__ b0in, const float* __restrict__ b1in,
    const float* __restrict__ b2in, const float* __restrict__ b3in,
    float* __restrict__ dense_out, int sel_base)
{
    extern __shared__ __nv_bfloat16 sh[];
    int tid = threadIdx.x;
    int sel = sel_base + blockIdx.z;
    int m0 = blockIdx.y * 128, n0 = blockIdx.x * 128;

    const __nv_bfloat16* Ahi = (sel < 3) ? g_xhi : g_chi;
    const __nv_bfloat16* Alo = (sel < 3) ? g_xlo : g_clo;
    const __nv_bfloat16* Bhi = g_whi + ((size_t)sel << 20);
    const __nv_bfloat16* Blo = g_wlo + ((size_t)sel << 20);
    const float* bias = sel==0 ? b0in : sel==1 ? b1in : sel==2 ? b2in : b3in;

    int wid = tid >> 5, lane = tid & 31;
    int warp_m = wid >> 2, warp_n = wid & 3;
    int gID = lane >> 2, tig = lane & 3;

    float acc[4][4][4];                 // [mf][nf][c0..c3]
    #pragma unroll
    for (int mf = 0; mf < 4; mf++)
        #pragma unroll
        for (int nf = 0; nf < 4; nf++)
            #pragma unroll
            for (int c = 0; c < 4; c++) acc[mf][nf][c] = 0.0f;

    for (int k0 = 0; k0 < EE; k0 += KC) {
        __syncthreads();
        // Stage A/B hi+lo tiles: 128 rows x 64 bf16, uint4 (8 bf16) granularity.
        #pragma unroll
        for (int it = 0; it < 4; it++) {
            int i = tid + it*256;       // 0..1023
            int r = i >> 3;
            int c8 = (i & 7) * 8;
            *(uint4*)&sh[SM_A_HI + r*SPITCH + c8] = *(const uint4*)(Ahi + (size_t)(m0+r)*EE + k0 + c8);
            *(uint4*)&sh[SM_A_LO + r*SPITCH + c8] = *(const uint4*)(Alo + (size_t)(m0+r)*EE + k0 + c8);
            *(uint4*)&sh[SM_B_HI + r*SPITCH + c8] = *(const uint4*)(Bhi + (size_t)(n0+r)*EE + k0 + c8);
            *(uint4*)&sh[SM_B_LO + r*SPITCH + c8] = *(const uint4*)(Blo + (size_t)(n0+r)*EE + k0 + c8);
        }
        __syncthreads();

        #pragma unroll
        for (int ks = 0; ks < KC/16; ks++) {
            int kc = ks*16 + 2*tig;
            // B fragments (hi+lo) for 4 n-frags
            uint32_t bh[4][2], bl[4][2];
            #pragma unroll
            for (int nf = 0; nf < 4; nf++) {
                int n = warp_n*32 + nf*8 + gID;
                bh[nf][0] = *(const uint32_t*)&sh[SM_B_HI + n*SPITCH + kc];
                bh[nf][1] = *(const uint32_t*)&sh[SM_B_HI + n*SPITCH + kc + 8];
                bl[nf][0] = *(const uint32_t*)&sh[SM_B_LO + n*SPITCH + kc];
                bl[nf][1] = *(const uint32_t*)&sh[SM_B_LO + n*SPITCH + kc + 8];
            }
            #pragma unroll
            for (int mf = 0; mf < 4; mf++) {
                int r = warp_m*64 + mf*16 + gID;
                uint32_t ah0 = *(const uint32_t*)&sh[SM_A_HI + r*SPITCH + kc];
                uint32_t ah1 = *(const uint32_t*)&sh[SM_A_HI + (r+8)*SPITCH + kc];
                uint32_t ah2 = *(const uint32_t*)&sh[SM_A_HI + r*SPITCH + kc + 8];
                uint32_t ah3 = *(const uint32_t*)&sh[SM_A_HI + (r+8)*SPITCH + kc + 8];
                uint32_t al0 = *(const uint32_t*)&sh[SM_A_LO + r*SPITCH + kc];
                uint32_t al1 = *(const uint32_t*)&sh[SM_A_LO + (r+8)*SPITCH + kc];
                uint32_t al2 = *(const uint32_t*)&sh[SM_A_LO + r*SPITCH + kc + 8];
                uint32_t al3 = *(const uint32_t*)&sh[SM_A_LO + (r+8)*SPITCH + kc + 8];
                #pragma unroll
                for (int nf = 0; nf < 4; nf++) {
                    hmma16816(acc[mf][nf], ah0, ah1, ah2, ah3, bh[nf][0], bh[nf][1]);
                    hmma16816(acc[mf][nf], ah0, ah1, ah2, ah3, bl[nf][0], bl[nf][1]);
                    hmma16816(acc[mf][nf], al0, al1, al2, al3, bh[nf][0], bh[nf][1]);
                }
            }
        }
    }

    // Epilogue
    float scale = (sel == 0) ? 0.125f : 1.0f;
    #pragma unroll
    for (int mf = 0; mf < 4; mf++) {
        int m = m0 + warp_m*64 + mf*16 + gID;     // rows m and m+8
        #pragma unroll
        for (int nf = 0; nf < 4; nf++) {
            int n = n0 + warp_n*32 + nf*8 + 2*tig;
            float bx = bias[n], by = bias[n+1];
            float2 lo = make_float2((acc[mf][nf][0] + bx) * scale,
                                    (acc[mf][nf][1] + by) * scale);
            float2 hi = make_float2((acc[mf][nf][2] + bx) * scale,
                                    (acc[mf][nf][3] + by) * scale);
            if (sel < 3) {
                float* dst = (sel == 0) ? g_q : (sel == 1) ? g_k : g_v;
                int h = n >> 6, d = n & 63;
                int b1 = m >> 11, t1 = m & (TT-1);
                *(float2*)&dst[(((size_t)(b1*HH + h))*TT + t1)*DD + d] = lo;
                int m2 = m + 8;
                int b2 = m2 >> 11, t2 = m2 & (TT-1);
                *(float2*)&dst[(((size_t)(b2*HH + h))*TT + t2)*DD + d] = hi;
            } else {
                *(float2*)&dense_out[(size_t)m*EE + n] = lo;
                *(float2*)&dense_out[(size_t)(m+8)*EE + n] = hi;
            }
        }
    }
}

// ---------------------------------------------------------------------------
// Position-bias table (unchanged)
// ---------------------------------------------------------------------------
__global__ void bias_table_kernel(const float* __restrict__ rel_embed)
{
    int idx = blockIdx.x * blockDim.x + threadIdx.x;
    if (idx >= BIAS_LEN) return;
    int delta = idx - (TT - 1);
    const int nb = 160;
    const int max_exact = 80;
    int rb = (delta > 0) ? nb : 0;
    int rel = abs(delta);
    int v;
    if (rel < max_exact) {
        v = rel;
    } else {
        float rf = (float)(rel < 1 ? 1 : rel);
        float large = logf(rf * (1.0f/80.0f)) * (float)(80.0 / 2.302585092994045684);
        int li = (int)((float)max_exact + large);
        v = li < (nb - 1) ? li : (nb - 1);
    }
    int bucket = rb + v;
    #pragma unroll
    for (int h = 0; h < HH; h++)
        g_bias[idx*HH + h] = rel_embed[bucket*HH + h];
}

// ---------------------------------------------------------------------------
// Gate (unchanged)
// ---------------------------------------------------------------------------
__global__ void gate_kernel(const float* __restrict__ hidden,
                            const float* __restrict__ gru_w,
                            const float* __restrict__ gru_b,
                            const float* __restrict__ gru_const)
{
    __shared__ float sw[8*DD];
    __shared__ float sb[8];
    __shared__ float sc[HH];
    int tid = threadIdx.x;
    for (int i = tid; i < 8*DD; i += blockDim.x) sw[i] = gru_w[i];
    if (tid < 8)    sb[tid] = gru_b[tid];
    if (tid < HH)   sc[tid] = gru_const[tid];
    __syncthreads();

    int i = blockIdx.x * blockDim.x + tid;
    if (i >= BB*TT*HH) return;
    int h  = i % HH;
    int bt = i / HH;
    const float* x = hidden + (size_t)bt*EE + h*DD;

    float p[8];
    #pragma unroll
    for (int j = 0; j < 8; j++) p[j] = sb[j];
    #pragma unroll
    for (int d = 0; d < DD; d += 4) {
        float4 xv = *(const float4*)&x[d];
        #pragma unroll
        for (int j = 0; j < 8; j++) {
            p[j] += xv.x*sw[j*DD+d] + xv.y*sw[j*DD+d+1]
                  + xv.z*sw[j*DD+d+2] + xv.w*sw[j*DD+d+3];
        }
    }
    float pa = p[0]+p[1]+p[2]+p[3];
    float pb = p[4]+p[5]+p[6]+p[7];
    float ga = 1.0f/(1.0f + __expf(-pa));
    float gb = 1.0f/(1.0f + __expf(-pb));
    float gout = ga*(gb*sc[h] - 1.0f) + 2.0f;
    int b = bt / TT, t = bt % TT;
    g_gate[(b*HH + h)*TT + t] = gout;
}

// ---------------------------------------------------------------------------
// Flash attention (unchanged SIMT version)
// ---------------------------------------------------------------------------
#define PITCH 68
#define ATTN_SMEM ((4*64*PITCH + 128 + 64) * (int)sizeof(float))

__global__ __launch_bounds__(256) void attn_kernel()
{
    extern __shared__ float smf[];
    float* Qs     = smf;
    float* Kst    = Qs  + 64*PITCH;
    float* Vs     = Kst + 64*PITCH;
    float* Ps     = Vs  + 64*PITCH;
    float* bias_s = Ps  + 64*PITCH;
    float* gate_s = bias_s + 128;

    int tid = threadIdx.x;
    int tx = tid & 15, ty = tid >> 4;
    int bh = blockIdx.y;
    int b = bh >> 4, h = bh & 15;
    int t0 = blockIdx.x * 64;

    const float* qbase = g_q + ((size_t)bh*TT + t0)*DD;
    const float* kbase = g_k + (size_t)bh*TT*DD;
    const float* vbase = g_v + (size_t)bh*TT*DD;

    {
        int r = tid >> 4;
        int c = (tid & 15) * 4;
        #pragma unroll
        for (int it = 0; it < 4; it++) {
            int row = it*16 + r;
            float4 v = *(const float4*)&qbase[(size_t)row*DD + c];
            float* p = &Qs[row*PITCH + c];
            p[0] = v.x; p[1] = v.y; p[2] = v.z; p[3] = v.w;
        }
    }
    if (tid < 64) gate_s[tid] = g_gate[(size_t)bh*TT + t0 + tid];

    float m_run[4], l_run[4];
    #pragma unroll
    for (int ri = 0; ri < 4; ri++) { m_run[ri] = -1e30f; l_run[ri] = 0.0f; }
    float oacc[4][4] = {};

    for (int s0 = 0; s0 < TT; s0 += 64) {
        __syncthreads();
        {
            int r = tid >> 4;
            int c = (tid & 15) * 4;
            #pragma unroll
            for (int it = 0; it < 4; it++) {
                int row = it*16 + r;
                float4 kv = *(const float4*)&kbase[(size_t)(s0+row)*DD + c];
                Kst[(c+0)*PITCH + row] = kv.x;
                Kst[(c+1)*PITCH + row] = kv.y;
                Kst[(c+2)*PITCH + row] = kv.z;
                Kst[(c+3)*PITCH + row] = kv.w;
                float4 vv = *(const float4*)&vbase[(size_t)(s0+row)*DD + c];
                float* p = &Vs[row*PITCH + c];
                p[0] = vv.x; p[1] = vv.y; p[2] = vv.z; p[3] = vv.w;
            }
        }
        if (tid < 128) {
            int gidx = s0 - t0 + tid - 63 + (TT - 1);
            bias_s[tid] = (gidx >= 0 && gidx < BIAS_LEN) ? g_bias[gidx*HH + h] : 0.0f;
        }
        __syncthreads();

        float s[4][4] = {};
        #pragma unroll
        for (int d0 = 0; d0 < DD; d0 += 4) {
            float4 q4[4];
            #pragma unroll
            for (int ri = 0; ri < 4; ri++)
                q4[ri] = *(const float4*)&Qs[(ty*4+ri)*PITCH + d0];
            #pragma unroll
            for (int dd = 0; dd < 4; dd++) {
                float4 k4 = *(const float4*)&Kst[(d0+dd)*PITCH + tx*4];
                #pragma unroll
                for (int ri = 0; ri < 4; ri++) {
                    float qv = dd==0 ? q4[ri].x : dd==1 ? q4[ri].y : dd==2 ? q4[ri].z : q4[ri].w;
                    s[ri][0] += qv*k4.x; s[ri][1] += qv*k4.y;
                    s[ri][2] += qv*k4.z; s[ri][3] += qv*k4.w;
                }
            }
        }

        #pragma unroll
        for (int ri = 0; ri < 4; ri++) {
            int row = ty*4 + ri;
            float g = gate_s[row];
            float rmax = -1e30f;
            #pragma unroll
            for (int cj = 0; cj < 4; cj++) {
                int j = tx*4 + cj;
                float val = s[ri][cj] + g * bias_s[j - row + 63];
                s[ri][cj] = val;
                rmax = fmaxf(rmax, val);
            }
            #pragma unroll
            for (int off = 8; off >= 1; off >>= 1)
                rmax = fmaxf(rmax, __shfl_xor_sync(0xffffffffu, rmax, off));
            float m_new = fmaxf(m_run[ri], rmax);
            float alpha = __expf(m_run[ri] - m_new);
            float rsum = 0.0f;
            float pv0, pv1, pv2, pv3;
            pv0 = __expf(s[ri][0] - m_new); rsum += pv0;
            pv1 = __expf(s[ri][1] - m_new); rsum += pv1;
            pv2 = __expf(s[ri][2] - m_new); rsum += pv2;
            pv3 = __expf(s[ri][3] - m_new); rsum += pv3;
            #pragma unroll
            for (int off = 8; off >= 1; off >>= 1)
                rsum += __shfl_xor_sync(0xffffffffu, rsum, off);
            l_run[ri] = l_run[ri]*alpha + rsum;
            m_run[ri] = m_new;
            #pragma unroll
            for (int ci = 0; ci < 4; ci++) oacc[ri][ci] *= alpha;
            float4 pq = make_float4(pv0, pv1, pv2, pv3);
            *(float4*)&Ps[row*PITCH + tx*4] = pq;
        }
        __syncthreads();

        #pragma unroll
        for (int j0 = 0; j0 < 64; j0 += 4) {
            float4 p4[4];
            #pragma unroll
            for (int ri = 0; ri < 4; ri++)
                p4[ri] = *(const float4*)&Ps[(ty*4+ri)*PITCH + j0];
            #pragma unroll
            for (int jj = 0; jj < 4; jj++) {
                float4 v4 = *(const float4*)&Vs[(j0+jj)*PITCH + tx*4];
                #pragma unroll
                for (int ri = 0; ri < 4; ri++) {
                    float pv = jj==0 ? p4[ri].x : jj==1 ? p4[ri].y : jj==2 ? p4[ri].z : p4[ri].w;
                    oacc[ri][0] += pv*v4.x; oacc[ri][1] += pv*v4.y;
                    oacc[ri][2] += pv*v4.z; oacc[ri][3] += pv*v4.w;
                }
            }
        }
    }

    #pragma unroll
    for (int ri = 0; ri < 4; ri++) {
        int t = t0 + ty*4 + ri;
        float inv = 1.0f / l_run[ri];
        float4 o = make_float4(oacc[ri][0]*inv, oacc[ri][1]*inv,
                               oacc[ri][2]*inv, oacc[ri][3]*inv);
        *(float4*)&g_ctx[((size_t)b*TT + t)*EE + h*DD + tx*4] = o;
    }
}

// ---------------------------------------------------------------------------
extern "C" void kernel_launch(void* const* d_in, const int* in_sizes, int n_in,
                              void* d_out, int out_size)
{
    const float* hidden    = (const float*)d_in[0];
    const float* q_w       = (const float*)d_in[1];
    const float* q_b       = (const float*)d_in[2];
    const float* k_w       = (const float*)d_in[3];
    const float* k_b       = (const float*)d_in[4];
    const float* v_w       = (const float*)d_in[5];
    const float* v_b       = (const float*)d_in[6];
    const float* out_w     = (const float*)d_in[7];
    const float* out_b     = (const float*)d_in[8];
    const float* rel_embed = (const float*)d_in[9];
    const float* gru_const = (const float*)d_in[10];
    const float* gru_w     = (const float*)d_in[11];
    const float* gru_b     = (const float*)d_in[12];
    float* out = (float*)d_out;

    bias_table_kernel<<<(BIAS_LEN + 255)/256, 256>>>(rel_embed);
    gate_kernel<<<(BB*TT*HH + 255)/256, 256>>>(hidden, gru_w, gru_b, gru_const);

    conv_x_kernel<<<(BT*EE/4 + 255)/256, 256>>>(hidden);
    conv_w_kernel<<<(4*EE*EE/4 + 255)/256, 256>>>(q_w, k_w, v_w, out_w);

    cudaFuncSetAttribute(hmma_gemm_kernel, cudaFuncAttributeMaxDynamicSharedMemorySize, GEMM_SMEM);
    hmma_gemm_kernel<<<dim3(EE/128, BT/128, 3), 256, GEMM_SMEM>>>(q_b, k_b, v_b, out_b, out, 0);

    cudaFuncSetAttribute(attn_kernel, cudaFuncAttributeMaxDynamicSharedMemorySize, ATTN_SMEM);
    attn_kernel<<<dim3(TT/64, BB*HH), 256, ATTN_SMEM>>>();

    conv_c_kernel<<<(BT*EE/4 + 255)/256, 256>>>();
    hmma_gemm_kernel<<<dim3(EE/128, BT/128, 1), 256, GEMM_SMEM>>>(q_b, k_b, v_b, out_b, out, 3);
}

// round 6
// speedup vs baseline: 2.4893x; 1.7850x over previous
#include <cuda_runtime.h>
#include <cuda_bf16.h>
#include <math.h>
#include <stdint.h>

#define BB 2
#define TT 2048
#define EE 1024
#define HH 16
#define DD 64
#define BT (BB*TT)            // 4096
#define BIAS_LEN (2*TT-1)     // 4095

// Scratch (device globals)
__device__ float g_ctx[BB*TT*EE];
__device__ float g_gate[BB*HH*TT];
__device__ float g_bias[BIAS_LEN*HH];
__device__ __nv_bfloat16 g_qhi[BB*HH*TT*DD], g_qlo[BB*HH*TT*DD];
__device__ __nv_bfloat16 g_khi[BB*HH*TT*DD], g_klo[BB*HH*TT*DD];
__device__ __nv_bfloat16 g_vhi[BB*HH*TT*DD], g_vlo[BB*HH*TT*DD];
__device__ __nv_bfloat16 g_xhi[BT*EE], g_xlo[BT*EE];
__device__ __nv_bfloat16 g_whi[4*EE*EE], g_wlo[4*EE*EE];
__device__ __nv_bfloat16 g_chi[BT*EE], g_clo[BT*EE];

// ===========================================================================
// helpers
// ===========================================================================
__device__ __forceinline__ uint32_t smem_u32(const void* p) {
    uint32_t a;
    asm("{ .reg .u64 t; cvta.to.shared.u64 t, %1; cvt.u32.u64 %0, t; }" : "=r"(a) : "l"(p));
    return a;
}
__device__ __forceinline__ void hmma16816(float c[4],
                                          uint32_t a0, uint32_t a1, uint32_t a2, uint32_t a3,
                                          uint32_t b0, uint32_t b1)
{
    asm volatile(
        "mma.sync.aligned.m16n8k16.row.col.f32.bf16.bf16.f32 "
        "{%0,%1,%2,%3}, {%4,%5,%6,%7}, {%8,%9}, {%0,%1,%2,%3};"
        : "+f"(c[0]), "+f"(c[1]), "+f"(c[2]), "+f"(c[3])
        : "r"(a0), "r"(a1), "r"(a2), "r"(a3), "r"(b0), "r"(b1));
}
// FMA-pipe exp (no MUFU)
__device__ __forceinline__ float fexp(float x) {
    x = fmaxf(x, -80.0f);
    float z = fmaf(x, 1.4426950408889634f, 12582912.0f);
    int n = __float_as_int(z) - 0x4B400000;
    float r = z - 12582912.0f;
    float f = fmaf(r, -0.6931471805599453f, x);
    float p = fmaf(f, 0.008333333f, 0.041666666f);
    p = fmaf(f, p, 0.16666667f);
    p = fmaf(f, p, 0.5f);
    p = fmaf(f, p, 1.0f);
    p = fmaf(f, p, 1.0f);
    return __int_as_float(__float_as_int(p) + (n << 23));
}
__device__ __forceinline__ uint32_t packbf2(float a, float b) {
    __nv_bfloat162 t = __floats2bfloat162_rn(a, b);
    return *(uint32_t*)&t;
}
// split x -> hi bf16 (returned packed) and residual floats
__device__ __forceinline__ void split2(float a, float b, uint32_t& hi, float& ra, float& rb) {
    __nv_bfloat16 ha = __float2bfloat16(a), hb = __float2bfloat16(b);
    __nv_bfloat162 t = {ha, hb};
    hi = *(uint32_t*)&t;
    ra = a - __bfloat162float(ha);
    rb = b - __bfloat162float(hb);
}

// ===========================================================================
// fp32 -> bf16 hi/lo conversions
// ===========================================================================
__global__ void conv_x_kernel(const float* __restrict__ src)
{
    int i = (blockIdx.x * blockDim.x + threadIdx.x) * 4;
    if (i >= BT*EE) return;
    float4 v = *(const float4*)&src[i];
    __nv_bfloat16 h0 = __float2bfloat16(v.x), h1 = __float2bfloat16(v.y);
    __nv_bfloat16 h2 = __float2bfloat16(v.z), h3 = __float2bfloat16(v.w);
    __nv_bfloat162 hp[2] = {{h0,h1},{h2,h3}};
    *(uint2*)&g_xhi[i] = *(uint2*)hp;
    __nv_bfloat162 lp[2] = {
        {__float2bfloat16(v.x - __bfloat162float(h0)), __float2bfloat16(v.y - __bfloat162float(h1))},
        {__float2bfloat16(v.z - __bfloat162float(h2)), __float2bfloat16(v.w - __bfloat162float(h3))}};
    *(uint2*)&g_xlo[i] = *(uint2*)lp;
}
__global__ void conv_w_kernel(const float* __restrict__ w0, const float* __restrict__ w1,
                              const float* __restrict__ w2, const float* __restrict__ w3)
{
    int i = (blockIdx.x * blockDim.x + threadIdx.x) * 4;
    if (i >= 4*EE*EE) return;
    int sel = i >> 20;
    const float* src = sel==0 ? w0 : sel==1 ? w1 : sel==2 ? w2 : w3;
    float4 v = *(const float4*)&src[i & ((1<<20)-1)];
    __nv_bfloat16 h0 = __float2bfloat16(v.x), h1 = __float2bfloat16(v.y);
    __nv_bfloat16 h2 = __float2bfloat16(v.z), h3 = __float2bfloat16(v.w);
    __nv_bfloat162 hp[2] = {{h0,h1},{h2,h3}};
    *(uint2*)&g_whi[i] = *(uint2*)hp;
    __nv_bfloat162 lp[2] = {
        {__float2bfloat16(v.x - __bfloat162float(h0)), __float2bfloat16(v.y - __bfloat162float(h1))},
        {__float2bfloat16(v.z - __bfloat162float(h2)), __float2bfloat16(v.w - __bfloat162float(h3))}};
    *(uint2*)&g_wlo[i] = *(uint2*)lp;
}
__global__ void conv_c_kernel()
{
    int i = (blockIdx.x * blockDim.x + threadIdx.x) * 4;
    if (i >= BT*EE) return;
    float4 v = *(const float4*)&g_ctx[i];
    __nv_bfloat16 h0 = __float2bfloat16(v.x), h1 = __float2bfloat16(v.y);
    __nv_bfloat16 h2 = __float2bfloat16(v.z), h3 = __float2bfloat16(v.w);
    __nv_bfloat162 hp[2] = {{h0,h1},{h2,h3}};
    *(uint2*)&g_chi[i] = *(uint2*)hp;
    __nv_bfloat162 lp[2] = {
        {__float2bfloat16(v.x - __bfloat162float(h0)), __float2bfloat16(v.y - __bfloat162float(h1))},
        {__float2bfloat16(v.z - __bfloat162float(h2)), __float2bfloat16(v.w - __bfloat162float(h3))}};
    *(uint2*)&g_clo[i] = *(uint2*)lp;
}

// ===========================================================================
// HMMA GEMM: 3-pass hi/lo, Y = A @ W^T + bias.
// sel 0/1/2 -> q/k/v written as bf16 hi/lo pairs in (B,H,T,D); sel 3 -> fp32.
// ===========================================================================
#define KC 64
#define SPITCH 72
#define SM_A_HI 0
#define SM_A_LO (128*SPITCH)
#define SM_B_HI (2*128*SPITCH)
#define SM_B_LO (3*128*SPITCH)
#define GEMM_SMEM (4*128*SPITCH*2)

__global__ __launch_bounds__(256) void hmma_gemm_kernel(
    const float* __restrict__ b0in, const float* __restrict__ b1in,
    const float* __restrict__ b2in, const float* __restrict__ b3in,
    float* __restrict__ dense_out, int sel_base)
{
    extern __shared__ __nv_bfloat16 sh[];
    int tid = threadIdx.x;
    int sel = sel_base + blockIdx.z;
    int m0 = blockIdx.y * 128, n0 = blockIdx.x * 128;

    const __nv_bfloat16* Ahi = (sel < 3) ? g_xhi : g_chi;
    const __nv_bfloat16* Alo = (sel < 3) ? g_xlo : g_clo;
    const __nv_bfloat16* Bhi = g_whi + ((size_t)sel << 20);
    const __nv_bfloat16* Blo = g_wlo + ((size_t)sel << 20);
    const float* bias = sel==0 ? b0in : sel==1 ? b1in : sel==2 ? b2in : b3in;

    int wid = tid >> 5, lane = tid & 31;
    int warp_m = wid >> 2, warp_n = wid & 3;
    int gID = lane >> 2, tig = lane & 3;

    float acc[4][4][4];
    #pragma unroll
    for (int mf = 0; mf < 4; mf++)
        #pragma unroll
        for (int nf = 0; nf < 4; nf++)
            #pragma unroll
            for (int c = 0; c < 4; c++) acc[mf][nf][c] = 0.0f;

    for (int k0 = 0; k0 < EE; k0 += KC) {
        __syncthreads();
        #pragma unroll
        for (int it = 0; it < 4; it++) {
            int i = tid + it*256;
            int r = i >> 3;
            int c8 = (i & 7) * 8;
            *(uint4*)&sh[SM_A_HI + r*SPITCH + c8] = *(const uint4*)(Ahi + (size_t)(m0+r)*EE + k0 + c8);
            *(uint4*)&sh[SM_A_LO + r*SPITCH + c8] = *(const uint4*)(Alo + (size_t)(m0+r)*EE + k0 + c8);
            *(uint4*)&sh[SM_B_HI + r*SPITCH + c8] = *(const uint4*)(Bhi + (size_t)(n0+r)*EE + k0 + c8);
            *(uint4*)&sh[SM_B_LO + r*SPITCH + c8] = *(const uint4*)(Blo + (size_t)(n0+r)*EE + k0 + c8);
        }
        __syncthreads();

        #pragma unroll
        for (int ks = 0; ks < KC/16; ks++) {
            int kc = ks*16 + 2*tig;
            uint32_t bh[4][2], bl[4][2];
            #pragma unroll
            for (int nf = 0; nf < 4; nf++) {
                int n = warp_n*32 + nf*8 + gID;
                bh[nf][0] = *(const uint32_t*)&sh[SM_B_HI + n*SPITCH + kc];
                bh[nf][1] = *(const uint32_t*)&sh[SM_B_HI + n*SPITCH + kc + 8];
                bl[nf][0] = *(const uint32_t*)&sh[SM_B_LO + n*SPITCH + kc];
                bl[nf][1] = *(const uint32_t*)&sh[SM_B_LO + n*SPITCH + kc + 8];
            }
            #pragma unroll
            for (int mf = 0; mf < 4; mf++) {
                int r = warp_m*64 + mf*16 + gID;
                uint32_t ah0 = *(const uint32_t*)&sh[SM_A_HI + r*SPITCH + kc];
                uint32_t ah1 = *(const uint32_t*)&sh[SM_A_HI + (r+8)*SPITCH + kc];
                uint32_t ah2 = *(const uint32_t*)&sh[SM_A_HI + r*SPITCH + kc + 8];
                uint32_t ah3 = *(const uint32_t*)&sh[SM_A_HI + (r+8)*SPITCH + kc + 8];
                uint32_t al0 = *(const uint32_t*)&sh[SM_A_LO + r*SPITCH + kc];
                uint32_t al1 = *(const uint32_t*)&sh[SM_A_LO + (r+8)*SPITCH + kc];
                uint32_t al2 = *(const uint32_t*)&sh[SM_A_LO + r*SPITCH + kc + 8];
                uint32_t al3 = *(const uint32_t*)&sh[SM_A_LO + (r+8)*SPITCH + kc + 8];
                #pragma unroll
                for (int nf = 0; nf < 4; nf++) {
                    hmma16816(acc[mf][nf], ah0, ah1, ah2, ah3, bh[nf][0], bh[nf][1]);
                    hmma16816(acc[mf][nf], ah0, ah1, ah2, ah3, bl[nf][0], bl[nf][1]);
                    hmma16816(acc[mf][nf], al0, al1, al2, al3, bh[nf][0], bh[nf][1]);
                }
            }
        }
    }

    float scale = (sel == 0) ? 0.125f : 1.0f;
    __nv_bfloat16* dh = (sel == 0) ? g_qhi : (sel == 1) ? g_khi : g_vhi;
    __nv_bfloat16* dl = (sel == 0) ? g_qlo : (sel == 1) ? g_klo : g_vlo;
    #pragma unroll
    for (int mf = 0; mf < 4; mf++) {
        int m = m0 + warp_m*64 + mf*16 + gID;
        #pragma unroll
        for (int nf = 0; nf < 4; nf++) {
            int n = n0 + warp_n*32 + nf*8 + 2*tig;
            float bx = bias[n], by = bias[n+1];
            if (sel < 3) {
                int h = n >> 6, d = n & 63;
                int b1 = m >> 11, t1 = m & (TT-1);
                int m2 = m + 8;
                int b2 = m2 >> 11, t2 = m2 & (TT-1);
                float v0 = (acc[mf][nf][0] + bx)*scale, v1 = (acc[mf][nf][1] + by)*scale;
                float v2 = (acc[mf][nf][2] + bx)*scale, v3 = (acc[mf][nf][3] + by)*scale;
                uint32_t h01, h23; float r0, r1, r2, r3;
                split2(v0, v1, h01, r0, r1);
                split2(v2, v3, h23, r2, r3);
                size_t o1 = (((size_t)(b1*HH + h))*TT + t1)*DD + d;
                size_t o2 = (((size_t)(b2*HH + h))*TT + t2)*DD + d;
                *(uint32_t*)&dh[o1] = h01;
                *(uint32_t*)&dh[o2] = h23;
                *(uint32_t*)&dl[o1] = packbf2(r0, r1);
                *(uint32_t*)&dl[o2] = packbf2(r2, r3);
            } else {
                float2 lo = make_float2(acc[mf][nf][0] + bx, acc[mf][nf][1] + by);
                float2 hi = make_float2(acc[mf][nf][2] + bx, acc[mf][nf][3] + by);
                *(float2*)&dense_out[(size_t)m*EE + n] = lo;
                *(float2*)&dense_out[(size_t)(m+8)*EE + n] = hi;
            }
        }
    }
}

// ---------------------------------------------------------------------------
// Position-bias table
// ---------------------------------------------------------------------------
__global__ void bias_table_kernel(const float* __restrict__ rel_embed)
{
    int idx = blockIdx.x * blockDim.x + threadIdx.x;
    if (idx >= BIAS_LEN) return;
    int delta = idx - (TT - 1);
    const int nb = 160;
    const int max_exact = 80;
    int rb = (delta > 0) ? nb : 0;
    int rel = abs(delta);
    int v;
    if (rel < max_exact) {
        v = rel;
    } else {
        float rf = (float)(rel < 1 ? 1 : rel);
        float large = logf(rf * (1.0f/80.0f)) * (float)(80.0 / 2.302585092994045684);
        int li = (int)((float)max_exact + large);
        v = li < (nb - 1) ? li : (nb - 1);
    }
    int bucket = rb + v;
    #pragma unroll
    for (int h = 0; h < HH; h++)
        g_bias[idx*HH + h] = rel_embed[bucket*HH + h];
}

// ---------------------------------------------------------------------------
// Gate
// ---------------------------------------------------------------------------
__global__ void gate_kernel(const float* __restrict__ hidden,
                            const float* __restrict__ gru_w,
                            const float* __restrict__ gru_b,
                            const float* __restrict__ gru_const)
{
    __shared__ float sw[8*DD];
    __shared__ float sb[8];
    __shared__ float sc[HH];
    int tid = threadIdx.x;
    for (int i = tid; i < 8*DD; i += blockDim.x) sw[i] = gru_w[i];
    if (tid < 8)    sb[tid] = gru_b[tid];
    if (tid < HH)   sc[tid] = gru_const[tid];
    __syncthreads();

    int i = blockIdx.x * blockDim.x + tid;
    if (i >= BB*TT*HH) return;
    int h  = i % HH;
    int bt = i / HH;
    const float* x = hidden + (size_t)bt*EE + h*DD;

    float p[8];
    #pragma unroll
    for (int j = 0; j < 8; j++) p[j] = sb[j];
    #pragma unroll
    for (int d = 0; d < DD; d += 4) {
        float4 xv = *(const float4*)&x[d];
        #pragma unroll
        for (int j = 0; j < 8; j++) {
            p[j] += xv.x*sw[j*DD+d] + xv.y*sw[j*DD+d+1]
                  + xv.z*sw[j*DD+d+2] + xv.w*sw[j*DD+d+3];
        }
    }
    float pa = p[0]+p[1]+p[2]+p[3];
    float pb = p[4]+p[5]+p[6]+p[7];
    float ga = 1.0f/(1.0f + __expf(-pa));
    float gb = 1.0f/(1.0f + __expf(-pb));
    float gout = ga*(gb*sc[h] - 1.0f) + 2.0f;
    int b = bt / TT, t = bt % TT;
    g_gate[(b*HH + h)*TT + t] = gout;
}

// ===========================================================================
// HMMA flash attention, 3-pass hi/lo everywhere.
// Block = 128 q-rows of one (b,h). 256 threads, 8 warps; warp owns 16 q-rows.
// ===========================================================================
#define AT_KP 72
#define AT_TILE (128*AT_KP)
#define ATTN_SMEM (4*AT_TILE*2 + 256*4 + 128*4)

__global__ __launch_bounds__(256) void attn_mma_kernel()
{
    extern __shared__ __nv_bfloat16 ash[];
    __nv_bfloat16* Ks_hi = ash;
    __nv_bfloat16* Ks_lo = ash + AT_TILE;
    __nv_bfloat16* Vs_hi = ash + 2*AT_TILE;
    __nv_bfloat16* Vs_lo = ash + 3*AT_TILE;
    float* bias_s = (float*)(ash + 4*AT_TILE);
    float* gate_s = bias_s + 256;

    int tid = threadIdx.x;
    int wid = tid >> 5, lane = tid & 31;
    int gID = lane >> 2, tig = lane & 3;
    int bh = blockIdx.y;
    int b = bh >> 4, h = bh & 15;
    int t0 = blockIdx.x * 128;

    const __nv_bfloat16* qh = g_qhi + ((size_t)bh*TT + t0)*DD;
    const __nv_bfloat16* ql = g_qlo + ((size_t)bh*TT + t0)*DD;
    const __nv_bfloat16* kh = g_khi + (size_t)bh*TT*DD;
    const __nv_bfloat16* kl = g_klo + (size_t)bh*TT*DD;
    const __nv_bfloat16* vh = g_vhi + (size_t)bh*TT*DD;
    const __nv_bfloat16* vl = g_vlo + (size_t)bh*TT*DD;

    // Q fragments (hi + lo) resident in registers
    uint32_t qah[4][4], qal[4][4];
    int qr0 = wid*16 + gID;
    #pragma unroll
    for (int ks = 0; ks < 4; ks++) {
        qah[ks][0] = *(const uint32_t*)&qh[(size_t)qr0*DD + ks*16 + 2*tig];
        qah[ks][1] = *(const uint32_t*)&qh[(size_t)(qr0+8)*DD + ks*16 + 2*tig];
        qah[ks][2] = *(const uint32_t*)&qh[(size_t)qr0*DD + ks*16 + 8 + 2*tig];
        qah[ks][3] = *(const uint32_t*)&qh[(size_t)(qr0+8)*DD + ks*16 + 8 + 2*tig];
        qal[ks][0] = *(const uint32_t*)&ql[(size_t)qr0*DD + ks*16 + 2*tig];
        qal[ks][1] = *(const uint32_t*)&ql[(size_t)(qr0+8)*DD + ks*16 + 2*tig];
        qal[ks][2] = *(const uint32_t*)&ql[(size_t)qr0*DD + ks*16 + 8 + 2*tig];
        qal[ks][3] = *(const uint32_t*)&ql[(size_t)(qr0+8)*DD + ks*16 + 8 + 2*tig];
    }
    if (tid < 128) gate_s[tid] = g_gate[(size_t)bh*TT + t0 + tid];
    __syncthreads();
    float g0 = gate_s[wid*16 + gID];
    float g1 = gate_s[wid*16 + gID + 8];

    float m0 = -1e30f, m1 = -1e30f, l0 = 0.0f, l1 = 0.0f;
    float oa[8][4];
    #pragma unroll
    for (int nf = 0; nf < 8; nf++)
        #pragma unroll
        for (int c = 0; c < 4; c++) oa[nf][c] = 0.0f;

    uint32_t kh_base = smem_u32(Ks_hi), kl_base = smem_u32(Ks_lo);
    uint32_t vh_base = smem_u32(Vs_hi), vl_base = smem_u32(Vs_lo);

    for (int s0 = 0; s0 < TT; s0 += 128) {
        __syncthreads();
        #pragma unroll
        for (int it = 0; it < 4; it++) {
            int i = tid + it*256;
            int r = i >> 3, c8 = (i & 7)*8;
            size_t go = (size_t)(s0+r)*DD + c8;
            *(uint4*)&Ks_hi[r*AT_KP + c8] = *(const uint4*)&kh[go];
            *(uint4*)&Ks_lo[r*AT_KP + c8] = *(const uint4*)&kl[go];
            *(uint4*)&Vs_hi[r*AT_KP + c8] = *(const uint4*)&vh[go];
            *(uint4*)&Vs_lo[r*AT_KP + c8] = *(const uint4*)&vl[go];
        }
        if (tid < 255) bias_s[tid] = g_bias[(size_t)(s0 - t0 - 127 + tid + TT - 1)*HH + h];
        __syncthreads();

        // ---- S = Q K^T, 3-pass
        float sc[16][4];
        #pragma unroll
        for (int nf = 0; nf < 16; nf++)
            #pragma unroll
            for (int c = 0; c < 4; c++) sc[nf][c] = 0.0f;

        #pragma unroll
        for (int ks = 0; ks < 4; ks++) {
            #pragma unroll
            for (int np = 0; np < 8; np++) {
                uint32_t rowoff = (((np*16 + ((lane>>4)<<3) + (lane&7))*AT_KP) + ks*16 + (((lane>>3)&1)<<3))*2;
                uint32_t rh0, rh1, rh2, rh3, rl0, rl1, rl2, rl3;
                asm volatile("ldmatrix.sync.aligned.m8n8.x4.shared.b16 {%0,%1,%2,%3}, [%4];"
                             : "=r"(rh0), "=r"(rh1), "=r"(rh2), "=r"(rh3) : "r"(kh_base + rowoff));
                asm volatile("ldmatrix.sync.aligned.m8n8.x4.shared.b16 {%0,%1,%2,%3}, [%4];"
                             : "=r"(rl0), "=r"(rl1), "=r"(rl2), "=r"(rl3) : "r"(kl_base + rowoff));
                hmma16816(sc[2*np],   qah[ks][0], qah[ks][1], qah[ks][2], qah[ks][3], rh0, rh1);
                hmma16816(sc[2*np],   qah[ks][0], qah[ks][1], qah[ks][2], qah[ks][3], rl0, rl1);
                hmma16816(sc[2*np],   qal[ks][0], qal[ks][1], qal[ks][2], qal[ks][3], rh0, rh1);
                hmma16816(sc[2*np+1], qah[ks][0], qah[ks][1], qah[ks][2], qah[ks][3], rh2, rh3);
                hmma16816(sc[2*np+1], qah[ks][0], qah[ks][1], qah[ks][2], qah[ks][3], rl2, rl3);
                hmma16816(sc[2*np+1], qal[ks][0], qal[ks][1], qal[ks][2], qal[ks][3], rh2, rh3);
            }
        }

        // ---- bias + online softmax
        float mx0 = -1e30f, mx1 = -1e30f;
        #pragma unroll
        for (int nf = 0; nf < 16; nf++) {
            int u = nf*8 + 2*tig - (wid*16 + gID) + 127;
            sc[nf][0] = fmaf(g0, bias_s[u],   sc[nf][0]);
            sc[nf][1] = fmaf(g0, bias_s[u+1], sc[nf][1]);
            sc[nf][2] = fmaf(g1, bias_s[u-8], sc[nf][2]);
            sc[nf][3] = fmaf(g1, bias_s[u-7], sc[nf][3]);
            mx0 = fmaxf(mx0, fmaxf(sc[nf][0], sc[nf][1]));
            mx1 = fmaxf(mx1, fmaxf(sc[nf][2], sc[nf][3]));
        }
        mx0 = fmaxf(mx0, __shfl_xor_sync(0xffffffffu, mx0, 1));
        mx0 = fmaxf(mx0, __shfl_xor_sync(0xffffffffu, mx0, 2));
        mx1 = fmaxf(mx1, __shfl_xor_sync(0xffffffffu, mx1, 1));
        mx1 = fmaxf(mx1, __shfl_xor_sync(0xffffffffu, mx1, 2));

        float mn0 = fmaxf(m0, mx0), mn1 = fmaxf(m1, mx1);
        float al0 = fexp(m0 - mn0), al1 = fexp(m1 - mn1);
        float ls0 = 0.0f, ls1 = 0.0f;
        #pragma unroll
        for (int nf = 0; nf < 16; nf++) {
            sc[nf][0] = fexp(sc[nf][0] - mn0); ls0 += sc[nf][0];
            sc[nf][1] = fexp(sc[nf][1] - mn0); ls0 += sc[nf][1];
            sc[nf][2] = fexp(sc[nf][2] - mn1); ls1 += sc[nf][2];
            sc[nf][3] = fexp(sc[nf][3] - mn1); ls1 += sc[nf][3];
        }
        ls0 += __shfl_xor_sync(0xffffffffu, ls0, 1);
        ls0 += __shfl_xor_sync(0xffffffffu, ls0, 2);
        ls1 += __shfl_xor_sync(0xffffffffu, ls1, 1);
        ls1 += __shfl_xor_sync(0xffffffffu, ls1, 2);
        l0 = l0*al0 + ls0;  l1 = l1*al1 + ls1;
        m0 = mn0;  m1 = mn1;
        #pragma unroll
        for (int nf = 0; nf < 8; nf++) {
            oa[nf][0] *= al0; oa[nf][1] *= al0;
            oa[nf][2] *= al1; oa[nf][3] *= al1;
        }

        // ---- O += P V, 3-pass (P split hi/lo in registers)
        #pragma unroll
        for (int ksp = 0; ksp < 8; ksp++) {
            uint32_t ph0, ph1, ph2, ph3;
            float r0a, r0b, r1a, r1b, r2a, r2b, r3a, r3b;
            split2(sc[2*ksp][0],   sc[2*ksp][1],   ph0, r0a, r0b);
            split2(sc[2*ksp][2],   sc[2*ksp][3],   ph1, r1a, r1b);
            split2(sc[2*ksp+1][0], sc[2*ksp+1][1], ph2, r2a, r2b);
            split2(sc[2*ksp+1][2], sc[2*ksp+1][3], ph3, r3a, r3b);
            uint32_t pl0 = packbf2(r0a, r0b), pl1 = packbf2(r1a, r1b);
            uint32_t pl2 = packbf2(r2a, r2b), pl3 = packbf2(r3a, r3b);
            #pragma unroll
            for (int np = 0; np < 4; np++) {
                uint32_t rowoff = (((16*ksp + (lane&15))*AT_KP) + np*16 + ((lane>>4)<<3))*2;
                uint32_t rh0, rh1, rh2, rh3, rl0, rl1, rl2, rl3;
                asm volatile("ldmatrix.sync.aligned.m8n8.x4.trans.shared.b16 {%0,%1,%2,%3}, [%4];"
                             : "=r"(rh0), "=r"(rh1), "=r"(rh2), "=r"(rh3) : "r"(vh_base + rowoff));
                asm volatile("ldmatrix.sync.aligned.m8n8.x4.trans.shared.b16 {%0,%1,%2,%3}, [%4];"
                             : "=r"(rl0), "=r"(rl1), "=r"(rl2), "=r"(rl3) : "r"(vl_base + rowoff));
                hmma16816(oa[2*np],   ph0, ph1, ph2, ph3, rh0, rh1);
                hmma16816(oa[2*np],   ph0, ph1, ph2, ph3, rl0, rl1);
                hmma16816(oa[2*np],   pl0, pl1, pl2, pl3, rh0, rh1);
                hmma16816(oa[2*np+1], ph0, ph1, ph2, ph3, rh2, rh3);
                hmma16816(oa[2*np+1], ph0, ph1, ph2, ph3, rl2, rl3);
                hmma16816(oa[2*np+1], pl0, pl1, pl2, pl3, rh2, rh3);
            }
        }
    }

    // epilogue: divide by l, write (B,T,E)
    float inv0 = 1.0f / l0, inv1 = 1.0f / l1;
    int t = t0 + wid*16 + gID;
    #pragma unroll
    for (int nf = 0; nf < 8; nf++) {
        int d = nf*8 + 2*tig;
        float2 v0 = make_float2(oa[nf][0]*inv0, oa[nf][1]*inv0);
        float2 v1 = make_float2(oa[nf][2]*inv1, oa[nf][3]*inv1);
        *(float2*)&g_ctx[((size_t)(b*TT + t))*EE + h*DD + d] = v0;
        *(float2*)&g_ctx[((size_t)(b*TT + t + 8))*EE + h*DD + d] = v1;
    }
}

// ---------------------------------------------------------------------------
extern "C" void kernel_launch(void* const* d_in, const int* in_sizes, int n_in,
                              void* d_out, int out_size)
{
    const float* hidden    = (const float*)d_in[0];
    const float* q_w       = (const float*)d_in[1];
    const float* q_b       = (const float*)d_in[2];
    const float* k_w       = (const float*)d_in[3];
    const float* k_b       = (const float*)d_in[4];
    const float* v_w       = (const float*)d_in[5];
    const float* v_b       = (const float*)d_in[6];
    const float* out_w     = (const float*)d_in[7];
    const float* out_b     = (const float*)d_in[8];
    const float* rel_embed = (const float*)d_in[9];
    const float* gru_const = (const float*)d_in[10];
    const float* gru_w     = (const float*)d_in[11];
    const float* gru_b     = (const float*)d_in[12];
    float* out = (float*)d_out;

    bias_table_kernel<<<(BIAS_LEN + 255)/256, 256>>>(rel_embed);
    gate_kernel<<<(BB*TT*HH + 255)/256, 256>>>(hidden, gru_w, gru_b, gru_const);

    conv_x_kernel<<<(BT*EE/4 + 255)/256, 256>>>(hidden);
    conv_w_kernel<<<(4*EE*EE/4 + 255)/256, 256>>>(q_w, k_w, v_w, out_w);

    cudaFuncSetAttribute(hmma_gemm_kernel, cudaFuncAttributeMaxDynamicSharedMemorySize, GEMM_SMEM);
    hmma_gemm_kernel<<<dim3(EE/128, BT/128, 3), 256, GEMM_SMEM>>>(q_b, k_b, v_b, out_b, out, 0);

    cudaFuncSetAttribute(attn_mma_kernel, cudaFuncAttributeMaxDynamicSharedMemorySize, ATTN_SMEM);
    attn_mma_kernel<<<dim3(TT/128, BB*HH), 256, ATTN_SMEM>>>();

    conv_c_kernel<<<(BT*EE/4 + 255)/256, 256>>>();
    hmma_gemm_kernel<<<dim3(EE/128, BT/128, 1), 256, GEMM_SMEM>>>(q_b, k_b, v_b, out_b, out, 3);
}

// round 7
// speedup vs baseline: 2.7035x; 1.0861x over previous
#include <cuda_runtime.h>
#include <cuda_bf16.h>
#include <math.h>
#include <stdint.h>

#define BB 2
#define TT 2048
#define EE 1024
#define HH 16
#define DD 64
#define BT (BB*TT)            // 4096
#define BIAS_LEN (2*TT-1)     // 4095

// Scratch (device globals)
__device__ float g_gate[BB*HH*TT];
__device__ float g_bias[BIAS_LEN*HH];
__device__ __nv_bfloat16 g_qhi[BB*HH*TT*DD], g_qlo[BB*HH*TT*DD];
__device__ __nv_bfloat16 g_khi[BB*HH*TT*DD], g_klo[BB*HH*TT*DD];
__device__ __nv_bfloat16 g_vhi[BB*HH*TT*DD], g_vlo[BB*HH*TT*DD];
__device__ __nv_bfloat16 g_xhi[BT*EE], g_xlo[BT*EE];
__device__ __nv_bfloat16 g_whi[4*EE*EE], g_wlo[4*EE*EE];
__device__ __nv_bfloat16 g_chi[BT*EE], g_clo[BT*EE];

// ===========================================================================
// helpers
// ===========================================================================
__device__ __forceinline__ uint32_t smem_u32(const void* p) {
    uint32_t a;
    asm("{ .reg .u64 t; cvta.to.shared.u64 t, %1; cvt.u32.u64 %0, t; }" : "=r"(a) : "l"(p));
    return a;
}
__device__ __forceinline__ void cp16(uint32_t dst, const void* src) {
    asm volatile("cp.async.ca.shared.global [%0], [%1], 16;" :: "r"(dst), "l"(src));
}
#define CP_COMMIT() asm volatile("cp.async.commit_group;" ::: "memory")
#define CP_WAIT1()  asm volatile("cp.async.wait_group 1;" ::: "memory")
#define CP_WAIT0()  asm volatile("cp.async.wait_group 0;" ::: "memory")

__device__ __forceinline__ void hmma16816(float c[4],
                                          uint32_t a0, uint32_t a1, uint32_t a2, uint32_t a3,
                                          uint32_t b0, uint32_t b1)
{
    asm volatile(
        "mma.sync.aligned.m16n8k16.row.col.f32.bf16.bf16.f32 "
        "{%0,%1,%2,%3}, {%4,%5,%6,%7}, {%8,%9}, {%0,%1,%2,%3};"
        : "+f"(c[0]), "+f"(c[1]), "+f"(c[2]), "+f"(c[3])
        : "r"(a0), "r"(a1), "r"(a2), "r"(a3), "r"(b0), "r"(b1));
}
// FMA-pipe exp (no MUFU)
__device__ __forceinline__ float fexp(float x) {
    x = fmaxf(x, -80.0f);
    float z = fmaf(x, 1.4426950408889634f, 12582912.0f);
    int n = __float_as_int(z) - 0x4B400000;
    float r = z - 12582912.0f;
    float f = fmaf(r, -0.6931471805599453f, x);
    float p = fmaf(f, 0.008333333f, 0.041666666f);
    p = fmaf(f, p, 0.16666667f);
    p = fmaf(f, p, 0.5f);
    p = fmaf(f, p, 1.0f);
    p = fmaf(f, p, 1.0f);
    return __int_as_float(__float_as_int(p) + (n << 23));
}
__device__ __forceinline__ uint32_t packbf2(float a, float b) {
    __nv_bfloat162 t = __floats2bfloat162_rn(a, b);
    return *(uint32_t*)&t;
}
__device__ __forceinline__ void split2(float a, float b, uint32_t& hi, float& ra, float& rb) {
    __nv_bfloat16 ha = __float2bfloat16(a), hb = __float2bfloat16(b);
    __nv_bfloat162 t = {ha, hb};
    hi = *(uint32_t*)&t;
    ra = a - __bfloat162float(ha);
    rb = b - __bfloat162float(hb);
}

// ===========================================================================
// fp32 -> bf16 hi/lo conversions
// ===========================================================================
__global__ void conv_x_kernel(const float* __restrict__ src)
{
    int i = (blockIdx.x * blockDim.x + threadIdx.x) * 4;
    if (i >= BT*EE) return;
    float4 v = *(const float4*)&src[i];
    __nv_bfloat16 h0 = __float2bfloat16(v.x), h1 = __float2bfloat16(v.y);
    __nv_bfloat16 h2 = __float2bfloat16(v.z), h3 = __float2bfloat16(v.w);
    __nv_bfloat162 hp[2] = {{h0,h1},{h2,h3}};
    *(uint2*)&g_xhi[i] = *(uint2*)hp;
    __nv_bfloat162 lp[2] = {
        {__float2bfloat16(v.x - __bfloat162float(h0)), __float2bfloat16(v.y - __bfloat162float(h1))},
        {__float2bfloat16(v.z - __bfloat162float(h2)), __float2bfloat16(v.w - __bfloat162float(h3))}};
    *(uint2*)&g_xlo[i] = *(uint2*)lp;
}
__global__ void conv_w_kernel(const float* __restrict__ w0, const float* __restrict__ w1,
                              const float* __restrict__ w2, const float* __restrict__ w3)
{
    int i = (blockIdx.x * blockDim.x + threadIdx.x) * 4;
    if (i >= 4*EE*EE) return;
    int sel = i >> 20;
    const float* src = sel==0 ? w0 : sel==1 ? w1 : sel==2 ? w2 : w3;
    float4 v = *(const float4*)&src[i & ((1<<20)-1)];
    __nv_bfloat16 h0 = __float2bfloat16(v.x), h1 = __float2bfloat16(v.y);
    __nv_bfloat16 h2 = __float2bfloat16(v.z), h3 = __float2bfloat16(v.w);
    __nv_bfloat162 hp[2] = {{h0,h1},{h2,h3}};
    *(uint2*)&g_whi[i] = *(uint2*)hp;
    __nv_bfloat162 lp[2] = {
        {__float2bfloat16(v.x - __bfloat162float(h0)), __float2bfloat16(v.y - __bfloat162float(h1))},
        {__float2bfloat16(v.z - __bfloat162float(h2)), __float2bfloat16(v.w - __bfloat162float(h3))}};
    *(uint2*)&g_wlo[i] = *(uint2*)lp;
}

// ===========================================================================
// HMMA GEMM, 3-pass hi/lo, cp.async 2-stage pipeline, KC=32.
// sel 0/1/2 -> q/k/v bf16 hi/lo (B,H,T,D); sel 3 -> fp32 dense out (A = ctx).
// ===========================================================================
#define KC 32
#define SPITCH 40
#define ARR (128*SPITCH)               // elems per array
#define STG (4*ARR)                    // elems per stage
#define GEMM_SMEM (2*STG*2)            // bytes

__global__ __launch_bounds__(256, 2) void hmma_gemm_kernel(
    const float* __restrict__ b0in, const float* __restrict__ b1in,
    const float* __restrict__ b2in, const float* __restrict__ b3in,
    float* __restrict__ dense_out, int sel_base)
{
    extern __shared__ __nv_bfloat16 sh[];
    int tid = threadIdx.x;
    int sel = sel_base + blockIdx.z;
    int m0 = blockIdx.y * 128, n0 = blockIdx.x * 128;

    const __nv_bfloat16* Ahi = (sel < 3) ? g_xhi : g_chi;
    const __nv_bfloat16* Alo = (sel < 3) ? g_xlo : g_clo;
    const __nv_bfloat16* Bhi = g_whi + ((size_t)sel << 20);
    const __nv_bfloat16* Blo = g_wlo + ((size_t)sel << 20);
    const float* bias = sel==0 ? b0in : sel==1 ? b1in : sel==2 ? b2in : b3in;

    int wid = tid >> 5, lane = tid & 31;
    int warp_m = wid >> 2, warp_n = wid & 3;
    int gID = lane >> 2, tig = lane & 3;
    uint32_t sb = smem_u32(sh);

    // per-thread cp.async slots: 8 x 16B, idx = tid + j*256 over 4 arrays
    int cp_arr[8], cp_r[8], cp_c8[8];
    #pragma unroll
    for (int j = 0; j < 8; j++) {
        int idx = tid + j*256;
        cp_arr[j] = idx >> 9;
        int c = idx & 511;
        cp_r[j] = c >> 2;
        cp_c8[j] = (c & 3) * 8;
    }

    float acc[4][4][4];
    #pragma unroll
    for (int mf = 0; mf < 4; mf++)
        #pragma unroll
        for (int nf = 0; nf < 4; nf++)
            #pragma unroll
            for (int c = 0; c < 4; c++) acc[mf][nf][c] = 0.0f;

    const int NK = EE / KC;   // 32

    // prefetch macro-ish lambda
    auto prefetch = [&](int kt, int stage) {
        int k0 = kt * KC;
        uint32_t stg = sb + (uint32_t)stage*STG*2;
        #pragma unroll
        for (int j = 0; j < 8; j++) {
            int a = cp_arr[j], r = cp_r[j], c8 = cp_c8[j];
            const __nv_bfloat16* src =
                (a == 0) ? (Ahi + (size_t)(m0+r)*EE + k0 + c8) :
                (a == 1) ? (Alo + (size_t)(m0+r)*EE + k0 + c8) :
                (a == 2) ? (Bhi + (size_t)(n0+r)*EE + k0 + c8) :
                           (Blo + (size_t)(n0+r)*EE + k0 + c8);
            cp16(stg + (uint32_t)(a*ARR + r*SPITCH + c8)*2, src);
        }
    };

    prefetch(0, 0);
    CP_COMMIT();

    for (int kt = 0; kt < NK; kt++) {
        int cur = kt & 1;
        if (kt + 1 < NK) { prefetch(kt+1, cur^1); CP_COMMIT(); CP_WAIT1(); }
        else             { CP_WAIT0(); }
        __syncthreads();

        const __nv_bfloat16* s = sh + cur*STG;
        #pragma unroll
        for (int ks = 0; ks < KC/16; ks++) {
            int kc = ks*16 + 2*tig;
            uint32_t bh[4][2], bl[4][2];
            #pragma unroll
            for (int nf = 0; nf < 4; nf++) {
                int n = warp_n*32 + nf*8 + gID;
                bh[nf][0] = *(const uint32_t*)&s[2*ARR + n*SPITCH + kc];
                bh[nf][1] = *(const uint32_t*)&s[2*ARR + n*SPITCH + kc + 8];
                bl[nf][0] = *(const uint32_t*)&s[3*ARR + n*SPITCH + kc];
                bl[nf][1] = *(const uint32_t*)&s[3*ARR + n*SPITCH + kc + 8];
            }
            #pragma unroll
            for (int mf = 0; mf < 4; mf++) {
                int r = warp_m*64 + mf*16 + gID;
                uint32_t ah0 = *(const uint32_t*)&s[r*SPITCH + kc];
                uint32_t ah1 = *(const uint32_t*)&s[(r+8)*SPITCH + kc];
                uint32_t ah2 = *(const uint32_t*)&s[r*SPITCH + kc + 8];
                uint32_t ah3 = *(const uint32_t*)&s[(r+8)*SPITCH + kc + 8];
                uint32_t al0 = *(const uint32_t*)&s[ARR + r*SPITCH + kc];
                uint32_t al1 = *(const uint32_t*)&s[ARR + (r+8)*SPITCH + kc];
                uint32_t al2 = *(const uint32_t*)&s[ARR + r*SPITCH + kc + 8];
                uint32_t al3 = *(const uint32_t*)&s[ARR + (r+8)*SPITCH + kc + 8];
                #pragma unroll
                for (int nf = 0; nf < 4; nf++) {
                    hmma16816(acc[mf][nf], ah0, ah1, ah2, ah3, bh[nf][0], bh[nf][1]);
                    hmma16816(acc[mf][nf], ah0, ah1, ah2, ah3, bl[nf][0], bl[nf][1]);
                    hmma16816(acc[mf][nf], al0, al1, al2, al3, bh[nf][0], bh[nf][1]);
                }
            }
        }
        __syncthreads();
    }

    float scale = (sel == 0) ? 0.125f : 1.0f;
    __nv_bfloat16* dh = (sel == 0) ? g_qhi : (sel == 1) ? g_khi : g_vhi;
    __nv_bfloat16* dl = (sel == 0) ? g_qlo : (sel == 1) ? g_klo : g_vlo;
    #pragma unroll
    for (int mf = 0; mf < 4; mf++) {
        int m = m0 + warp_m*64 + mf*16 + gID;
        #pragma unroll
        for (int nf = 0; nf < 4; nf++) {
            int n = n0 + warp_n*32 + nf*8 + 2*tig;
            float bx = bias[n], by = bias[n+1];
            if (sel < 3) {
                int h = n >> 6, d = n & 63;
                int b1 = m >> 11, t1 = m & (TT-1);
                int m2 = m + 8;
                int b2 = m2 >> 11, t2 = m2 & (TT-1);
                float v0 = (acc[mf][nf][0] + bx)*scale, v1 = (acc[mf][nf][1] + by)*scale;
                float v2 = (acc[mf][nf][2] + bx)*scale, v3 = (acc[mf][nf][3] + by)*scale;
                uint32_t h01, h23; float r0, r1, r2, r3;
                split2(v0, v1, h01, r0, r1);
                split2(v2, v3, h23, r2, r3);
                size_t o1 = (((size_t)(b1*HH + h))*TT + t1)*DD + d;
                size_t o2 = (((size_t)(b2*HH + h))*TT + t2)*DD + d;
                *(uint32_t*)&dh[o1] = h01;
                *(uint32_t*)&dh[o2] = h23;
                *(uint32_t*)&dl[o1] = packbf2(r0, r1);
                *(uint32_t*)&dl[o2] = packbf2(r2, r3);
            } else {
                float2 lo = make_float2(acc[mf][nf][0] + bx, acc[mf][nf][1] + by);
                float2 hi = make_float2(acc[mf][nf][2] + bx, acc[mf][nf][3] + by);
                *(float2*)&dense_out[(size_t)m*EE + n] = lo;
                *(float2*)&dense_out[(size_t)(m+8)*EE + n] = hi;
            }
        }
    }
}

// ---------------------------------------------------------------------------
// Position-bias table
// ---------------------------------------------------------------------------
__global__ void bias_table_kernel(const float* __restrict__ rel_embed)
{
    int idx = blockIdx.x * blockDim.x + threadIdx.x;
    if (idx >= BIAS_LEN) return;
    int delta = idx - (TT - 1);
    const int nb = 160;
    const int max_exact = 80;
    int rb = (delta > 0) ? nb : 0;
    int rel = abs(delta);
    int v;
    if (rel < max_exact) {
        v = rel;
    } else {
        float rf = (float)(rel < 1 ? 1 : rel);
        float large = logf(rf * (1.0f/80.0f)) * (float)(80.0 / 2.302585092994045684);
        int li = (int)((float)max_exact + large);
        v = li < (nb - 1) ? li : (nb - 1);
    }
    int bucket = rb + v;
    #pragma unroll
    for (int h = 0; h < HH; h++)
        g_bias[idx*HH + h] = rel_embed[bucket*HH + h];
}

// ---------------------------------------------------------------------------
// Gate
// ---------------------------------------------------------------------------
__global__ void gate_kernel(const float* __restrict__ hidden,
                            const float* __restrict__ gru_w,
                            const float* __restrict__ gru_b,
                            const float* __restrict__ gru_const)
{
    __shared__ float sw[8*DD];
    __shared__ float sb[8];
    __shared__ float sc[HH];
    int tid = threadIdx.x;
    for (int i = tid; i < 8*DD; i += blockDim.x) sw[i] = gru_w[i];
    if (tid < 8)    sb[tid] = gru_b[tid];
    if (tid < HH)   sc[tid] = gru_const[tid];
    __syncthreads();

    int i = blockIdx.x * blockDim.x + tid;
    if (i >= BB*TT*HH) return;
    int h  = i % HH;
    int bt = i / HH;
    const float* x = hidden + (size_t)bt*EE + h*DD;

    float p[8];
    #pragma unroll
    for (int j = 0; j < 8; j++) p[j] = sb[j];
    #pragma unroll
    for (int d = 0; d < DD; d += 4) {
        float4 xv = *(const float4*)&x[d];
        #pragma unroll
        for (int j = 0; j < 8; j++) {
            p[j] += xv.x*sw[j*DD+d] + xv.y*sw[j*DD+d+1]
                  + xv.z*sw[j*DD+d+2] + xv.w*sw[j*DD+d+3];
        }
    }
    float pa = p[0]+p[1]+p[2]+p[3];
    float pb = p[4]+p[5]+p[6]+p[7];
    float ga = 1.0f/(1.0f + __expf(-pa));
    float gb = 1.0f/(1.0f + __expf(-pb));
    float gout = ga*(gb*sc[h] - 1.0f) + 2.0f;
    int b = bt / TT, t = bt % TT;
    g_gate[(b*HH + h)*TT + t] = gout;
}

// ===========================================================================
// HMMA flash attention, 3-pass hi/lo, cp.async 2-stage, KV chunk 64.
// Block = 128 q-rows of one (b,h). 256 threads, 8 warps; warp owns 16 q-rows.
// Epilogue writes ctx directly as bf16 hi/lo.
// ===========================================================================
#define AT_KP 72
#define AT_TILE (64*AT_KP)             // elems per array per stage
#define AT_STG (4*AT_TILE)             // elems per stage
#define ATTN_SMEM (2*AT_STG*2 + 2*192*4 + 128*4)

__global__ __launch_bounds__(256, 2) void attn_mma_kernel()
{
    extern __shared__ __nv_bfloat16 ash[];
    float* bias_s = (float*)(ash + 2*AT_STG);    // [2][192]
    float* gate_s = bias_s + 2*192;              // [128]

    int tid = threadIdx.x;
    int wid = tid >> 5, lane = tid & 31;
    int gID = lane >> 2, tig = lane & 3;
    int bh = blockIdx.y;
    int b = bh >> 4, h = bh & 15;
    int t0 = blockIdx.x * 128;

    const __nv_bfloat16* qh = g_qhi + ((size_t)bh*TT + t0)*DD;
    const __nv_bfloat16* ql = g_qlo + ((size_t)bh*TT + t0)*DD;
    const __nv_bfloat16* kh = g_khi + (size_t)bh*TT*DD;
    const __nv_bfloat16* kl = g_klo + (size_t)bh*TT*DD;
    const __nv_bfloat16* vh = g_vhi + (size_t)bh*TT*DD;
    const __nv_bfloat16* vl = g_vlo + (size_t)bh*TT*DD;

    // Q fragments (hi + lo) in registers
    uint32_t qah[4][4], qal[4][4];
    int qr0 = wid*16 + gID;
    #pragma unroll
    for (int ks = 0; ks < 4; ks++) {
        qah[ks][0] = *(const uint32_t*)&qh[(size_t)qr0*DD + ks*16 + 2*tig];
        qah[ks][1] = *(const uint32_t*)&qh[(size_t)(qr0+8)*DD + ks*16 + 2*tig];
        qah[ks][2] = *(const uint32_t*)&qh[(size_t)qr0*DD + ks*16 + 8 + 2*tig];
        qah[ks][3] = *(const uint32_t*)&qh[(size_t)(qr0+8)*DD + ks*16 + 8 + 2*tig];
        qal[ks][0] = *(const uint32_t*)&ql[(size_t)qr0*DD + ks*16 + 2*tig];
        qal[ks][1] = *(const uint32_t*)&ql[(size_t)(qr0+8)*DD + ks*16 + 2*tig];
        qal[ks][2] = *(const uint32_t*)&ql[(size_t)qr0*DD + ks*16 + 8 + 2*tig];
        qal[ks][3] = *(const uint32_t*)&ql[(size_t)(qr0+8)*DD + ks*16 + 8 + 2*tig];
    }
    if (tid < 128) gate_s[tid] = g_gate[(size_t)bh*TT + t0 + tid];
    float g0_ = g_gate[(size_t)bh*TT + t0 + wid*16 + gID];
    float g1_ = g_gate[(size_t)bh*TT + t0 + wid*16 + gID + 8];

    float m0 = -1e30f, m1 = -1e30f, l0 = 0.0f, l1 = 0.0f;
    float oa[8][4];
    #pragma unroll
    for (int nf = 0; nf < 8; nf++)
        #pragma unroll
        for (int c = 0; c < 4; c++) oa[nf][c] = 0.0f;

    uint32_t sb = smem_u32(ash);

    // per-thread cp.async slots: 4 arrays x 64x64 = 16K elems = 2048 x 16B; 8/thread
    // idx = tid + j*256: arr = idx>>9, c = idx&511: r = c>>3, c8 = (c&7)*8
    auto loadKV = [&](int s0, int stage) {
        uint32_t stg = sb + (uint32_t)stage*AT_STG*2;
        #pragma unroll
        for (int j = 0; j < 8; j++) {
            int idx = tid + j*256;
            int a = idx >> 9;
            int c = idx & 511;
            int r = c >> 3, c8 = (c & 7)*8;
            size_t go = (size_t)(s0+r)*DD + c8;
            const __nv_bfloat16* src = (a==0) ? kh+go : (a==1) ? kl+go : (a==2) ? vh+go : vl+go;
            cp16(stg + (uint32_t)(a*AT_TILE + r*AT_KP + c8)*2, src);
        }
    };

    const int NC = TT/64;   // 32
    loadKV(0, 0);
    CP_COMMIT();

    for (int ch = 0; ch < NC; ch++) {
        int cur = ch & 1;
        int s0 = ch * 64;
        if (ch + 1 < NC) { loadKV(s0 + 64, cur^1); CP_COMMIT(); CP_WAIT1(); }
        else             { CP_WAIT0(); }
        // bias window for this chunk into bias_s[cur][0..190]
        if (tid < 191)
            bias_s[cur*192 + tid] = g_bias[(size_t)(s0 - t0 - 127 + tid + TT - 1)*HH + h];
        __syncthreads();

        const __nv_bfloat16* st = ash + cur*AT_STG;
        uint32_t kh_b = sb + (uint32_t)(cur*AT_STG)*2;
        uint32_t kl_b = kh_b + AT_TILE*2;
        uint32_t vh_b = kh_b + 2*AT_TILE*2;
        uint32_t vl_b = kh_b + 3*AT_TILE*2;
        const float* bw = bias_s + cur*192;

        // ---- S = Q K^T, 3-pass: sc[8 n-frags][4]
        float sc[8][4];
        #pragma unroll
        for (int nf = 0; nf < 8; nf++)
            #pragma unroll
            for (int c = 0; c < 4; c++) sc[nf][c] = 0.0f;

        #pragma unroll
        for (int ks = 0; ks < 4; ks++) {
            #pragma unroll
            for (int np = 0; np < 4; np++) {
                uint32_t rowoff = (((np*16 + ((lane>>4)<<3) + (lane&7))*AT_KP) + ks*16 + (((lane>>3)&1)<<3))*2;
                uint32_t rh0, rh1, rh2, rh3, rl0, rl1, rl2, rl3;
                asm volatile("ldmatrix.sync.aligned.m8n8.x4.shared.b16 {%0,%1,%2,%3}, [%4];"
                             : "=r"(rh0), "=r"(rh1), "=r"(rh2), "=r"(rh3) : "r"(kh_b + rowoff));
                asm volatile("ldmatrix.sync.aligned.m8n8.x4.shared.b16 {%0,%1,%2,%3}, [%4];"
                             : "=r"(rl0), "=r"(rl1), "=r"(rl2), "=r"(rl3) : "r"(kl_b + rowoff));
                hmma16816(sc[2*np],   qah[ks][0], qah[ks][1], qah[ks][2], qah[ks][3], rh0, rh1);
                hmma16816(sc[2*np],   qah[ks][0], qah[ks][1], qah[ks][2], qah[ks][3], rl0, rl1);
                hmma16816(sc[2*np],   qal[ks][0], qal[ks][1], qal[ks][2], qal[ks][3], rh0, rh1);
                hmma16816(sc[2*np+1], qah[ks][0], qah[ks][1], qah[ks][2], qah[ks][3], rh2, rh3);
                hmma16816(sc[2*np+1], qah[ks][0], qah[ks][1], qah[ks][2], qah[ks][3], rl2, rl3);
                hmma16816(sc[2*np+1], qal[ks][0], qal[ks][1], qal[ks][2], qal[ks][3], rh2, rh3);
            }
        }

        // ---- bias + online softmax
        float mx0 = -1e30f, mx1 = -1e30f;
        #pragma unroll
        for (int nf = 0; nf < 8; nf++) {
            int u = nf*8 + 2*tig - (wid*16 + gID) + 127;
            sc[nf][0] = fmaf(g0_, bw[u],   sc[nf][0]);
            sc[nf][1] = fmaf(g0_, bw[u+1], sc[nf][1]);
            sc[nf][2] = fmaf(g1_, bw[u-8], sc[nf][2]);
            sc[nf][3] = fmaf(g1_, bw[u-7], sc[nf][3]);
            mx0 = fmaxf(mx0, fmaxf(sc[nf][0], sc[nf][1]));
            mx1 = fmaxf(mx1, fmaxf(sc[nf][2], sc[nf][3]));
        }
        mx0 = fmaxf(mx0, __shfl_xor_sync(0xffffffffu, mx0, 1));
        mx0 = fmaxf(mx0, __shfl_xor_sync(0xffffffffu, mx0, 2));
        mx1 = fmaxf(mx1, __shfl_xor_sync(0xffffffffu, mx1, 1));
        mx1 = fmaxf(mx1, __shfl_xor_sync(0xffffffffu, mx1, 2));

        float mn0 = fmaxf(m0, mx0), mn1 = fmaxf(m1, mx1);
        float al0 = fexp(m0 - mn0), al1 = fexp(m1 - mn1);
        float ls0 = 0.0f, ls1 = 0.0f;
        #pragma unroll
        for (int nf = 0; nf < 8; nf++) {
            sc[nf][0] = fexp(sc[nf][0] - mn0); ls0 += sc[nf][0];
            sc[nf][1] = fexp(sc[nf][1] - mn0); ls0 += sc[nf][1];
            sc[nf][2] = fexp(sc[nf][2] - mn1); ls1 += sc[nf][2];
            sc[nf][3] = fexp(sc[nf][3] - mn1); ls1 += sc[nf][3];
        }
        ls0 += __shfl_xor_sync(0xffffffffu, ls0, 1);
        ls0 += __shfl_xor_sync(0xffffffffu, ls0, 2);
        ls1 += __shfl_xor_sync(0xffffffffu, ls1, 1);
        ls1 += __shfl_xor_sync(0xffffffffu, ls1, 2);
        l0 = l0*al0 + ls0;  l1 = l1*al1 + ls1;
        m0 = mn0;  m1 = mn1;
        #pragma unroll
        for (int nf = 0; nf < 8; nf++) {
            oa[nf][0] *= al0; oa[nf][1] *= al0;
            oa[nf][2] *= al1; oa[nf][3] *= al1;
        }

        // ---- O += P V, 3-pass
        #pragma unroll
        for (int ksp = 0; ksp < 4; ksp++) {
            uint32_t ph0, ph1, ph2, ph3;
            float r0a, r0b, r1a, r1b, r2a, r2b, r3a, r3b;
            split2(sc[2*ksp][0],   sc[2*ksp][1],   ph0, r0a, r0b);
            split2(sc[2*ksp][2],   sc[2*ksp][3],   ph1, r1a, r1b);
            split2(sc[2*ksp+1][0], sc[2*ksp+1][1], ph2, r2a, r2b);
            split2(sc[2*ksp+1][2], sc[2*ksp+1][3], ph3, r3a, r3b);
            uint32_t pl0 = packbf2(r0a, r0b), pl1 = packbf2(r1a, r1b);
            uint32_t pl2 = packbf2(r2a, r2b), pl3 = packbf2(r3a, r3b);
            #pragma unroll
            for (int np = 0; np < 4; np++) {
                uint32_t rowoff = (((16*ksp + (lane&15))*AT_KP) + np*16 + ((lane>>4)<<3))*2;
                uint32_t rh0, rh1, rh2, rh3, rl0, rl1, rl2, rl3;
                asm volatile("ldmatrix.sync.aligned.m8n8.x4.trans.shared.b16 {%0,%1,%2,%3}, [%4];"
                             : "=r"(rh0), "=r"(rh1), "=r"(rh2), "=r"(rh3) : "r"(vh_b + rowoff));
                asm volatile("ldmatrix.sync.aligned.m8n8.x4.trans.shared.b16 {%0,%1,%2,%3}, [%4];"
                             : "=r"(rl0), "=r"(rl1), "=r"(rl2), "=r"(rl3) : "r"(vl_b + rowoff));
                hmma16816(oa[2*np],   ph0, ph1, ph2, ph3, rh0, rh1);
                hmma16816(oa[2*np],   ph0, ph1, ph2, ph3, rl0, rl1);
                hmma16816(oa[2*np],   pl0, pl1, pl2, pl3, rh0, rh1);
                hmma16816(oa[2*np+1], ph0, ph1, ph2, ph3, rh2, rh3);
                hmma16816(oa[2*np+1], ph0, ph1, ph2, ph3, rl2, rl3);
                hmma16816(oa[2*np+1], pl0, pl1, pl2, pl3, rh2, rh3);
            }
        }
        __syncthreads();
    }

    // epilogue: divide by l, write ctx as bf16 hi/lo
    float inv0 = 1.0f / l0, inv1 = 1.0f / l1;
    int t = t0 + wid*16 + gID;
    #pragma unroll
    for (int nf = 0; nf < 8; nf++) {
        int d = nf*8 + 2*tig;
        float v0x = oa[nf][0]*inv0, v0y = oa[nf][1]*inv0;
        float v1x = oa[nf][2]*inv1, v1y = oa[nf][3]*inv1;
        uint32_t h0, h1; float r0a, r0b, r1a, r1b;
        split2(v0x, v0y, h0, r0a, r0b);
        split2(v1x, v1y, h1, r1a, r1b);
        size_t o0 = ((size_t)(b*TT + t))*EE + h*DD + d;
        size_t o1 = ((size_t)(b*TT + t + 8))*EE + h*DD + d;
        *(uint32_t*)&g_chi[o0] = h0;
        *(uint32_t*)&g_chi[o1] = h1;
        *(uint32_t*)&g_clo[o0] = packbf2(r0a, r0b);
        *(uint32_t*)&g_clo[o1] = packbf2(r1a, r1b);
    }
}

// ---------------------------------------------------------------------------
extern "C" void kernel_launch(void* const* d_in, const int* in_sizes, int n_in,
                              void* d_out, int out_size)
{
    const float* hidden    = (const float*)d_in[0];
    const float* q_w       = (const float*)d_in[1];
    const float* q_b       = (const float*)d_in[2];
    const float* k_w       = (const float*)d_in[3];
    const float* k_b       = (const float*)d_in[4];
    const float* v_w       = (const float*)d_in[5];
    const float* v_b       = (const float*)d_in[6];
    const float* out_w     = (const float*)d_in[7];
    const float* out_b     = (const float*)d_in[8];
    const float* rel_embed = (const float*)d_in[9];
    const float* gru_const = (const float*)d_in[10];
    const float* gru_w     = (const float*)d_in[11];
    const float* gru_b     = (const float*)d_in[12];
    float* out = (float*)d_out;

    bias_table_kernel<<<(BIAS_LEN + 255)/256, 256>>>(rel_embed);
    gate_kernel<<<(BB*TT*HH + 255)/256, 256>>>(hidden, gru_w, gru_b, gru_const);

    conv_x_kernel<<<(BT*EE/4 + 255)/256, 256>>>(hidden);
    conv_w_kernel<<<(4*EE*EE/4 + 255)/256, 256>>>(q_w, k_w, v_w, out_w);

    cudaFuncSetAttribute(hmma_gemm_kernel, cudaFuncAttributeMaxDynamicSharedMemorySize, GEMM_SMEM);
    hmma_gemm_kernel<<<dim3(EE/128, BT/128, 3), 256, GEMM_SMEM>>>(q_b, k_b, v_b, out_b, out, 0);

    cudaFuncSetAttribute(attn_mma_kernel, cudaFuncAttributeMaxDynamicSharedMemorySize, ATTN_SMEM);
    attn_mma_kernel<<<dim3(TT/128, BB*HH), 256, ATTN_SMEM>>>();

    hmma_gemm_kernel<<<dim3(EE/128, BT/128, 1), 256, GEMM_SMEM>>>(q_b, k_b, v_b, out_b, out, 3);
}

// round 11
// speedup vs baseline: 3.2993x; 1.2204x over previous
#include <cuda_runtime.h>
#include <cuda_fp16.h>
#include <math.h>
#include <stdint.h>

#define BB 2
#define TT 2048
#define EE 1024
#define HH 16
#define DD 64
#define BT (BB*TT)            // 4096
#define BIAS_LEN (2*TT-1)     // 4095

// Scratch (device globals)
__device__ float g_gate[BB*HH*TT];
__device__ float g_bias[BIAS_LEN*HH];
__device__ __half g_qhi[BB*HH*TT*DD], g_qlo[BB*HH*TT*DD];
__device__ __half g_kh[BB*HH*TT*DD];
__device__ __half g_vh[BB*HH*TT*DD];
__device__ __half g_xhi[BT*EE], g_xlo[BT*EE];
__device__ __half g_whi[4*EE*EE], g_wlo[4*EE*EE];
__device__ __half g_chi[BT*EE], g_clo[BT*EE];

// ===========================================================================
// helpers
// ===========================================================================
__device__ __forceinline__ uint32_t smem_u32(const void* p) {
    uint32_t a;
    asm("{ .reg .u64 t; cvta.to.shared.u64 t, %1; cvt.u32.u64 %0, t; }" : "=r"(a) : "l"(p));
    return a;
}
__device__ __forceinline__ void cp16(uint32_t dst, const void* src) {
    asm volatile("cp.async.ca.shared.global [%0], [%1], 16;" :: "r"(dst), "l"(src));
}
#define CP_COMMIT() asm volatile("cp.async.commit_group;" ::: "memory")
#define CP_WAIT1()  asm volatile("cp.async.wait_group 1;" ::: "memory")
#define CP_WAIT0()  asm volatile("cp.async.wait_group 0;" ::: "memory")

__device__ __forceinline__ void hmma16816(float c[4],
                                          uint32_t a0, uint32_t a1, uint32_t a2, uint32_t a3,
                                          uint32_t b0, uint32_t b1)
{
    asm volatile(
        "mma.sync.aligned.m16n8k16.row.col.f32.f16.f16.f32 "
        "{%0,%1,%2,%3}, {%4,%5,%6,%7}, {%8,%9}, {%0,%1,%2,%3};"
        : "+f"(c[0]), "+f"(c[1]), "+f"(c[2]), "+f"(c[3])
        : "r"(a0), "r"(a1), "r"(a2), "r"(a3), "r"(b0), "r"(b1));
}
// FMA-pipe exp (no MUFU); args here are <= 0 (online-max softmax)
__device__ __forceinline__ float fexp(float x) {
    x = fmaxf(x, -80.0f);
    float z = fmaf(x, 1.4426950408889634f, 12582912.0f);
    int n = __float_as_int(z) - 0x4B400000;
    float r = z - 12582912.0f;
    float f = fmaf(r, -0.6931471805599453f, x);
    float p = fmaf(f, 0.008333333f, 0.041666666f);
    p = fmaf(f, p, 0.16666667f);
    p = fmaf(f, p, 0.5f);
    p = fmaf(f, p, 1.0f);
    p = fmaf(f, p, 1.0f);
    return __int_as_float(__float_as_int(p) + (n << 23));
}
__device__ __forceinline__ uint32_t packh2(float a, float b) {
    __half2 t = __floats2half2_rn(a, b);
    return *(uint32_t*)&t;
}
__device__ __forceinline__ void splith2(float a, float b, uint32_t& hi, uint32_t& lo) {
    __half ha = __float2half_rn(a), hb = __float2half_rn(b);
    __half2 t{ha, hb};
    hi = *(uint32_t*)&t;
    lo = packh2(a - __half2float(ha), b - __half2float(hb));
}

// ===========================================================================
// Fused prep: conv_x | conv_w | gate | bias_table, selected by blockIdx.x
// FIX: PREP_GT = 256 (BB*TT*HH / 256 = 65536/256) — was 128, leaving half
// of g_gate unwritten (the R8-R10 1.9e-2 failure).
// ===========================================================================
#define PREP_CX 4096
#define PREP_CW 4096
#define PREP_GT 256
#define PREP_BT 16
#define PREP_BLOCKS (PREP_CX + PREP_CW + PREP_GT + PREP_BT)

__global__ __launch_bounds__(256) void prep_kernel(
    const float* __restrict__ hidden,
    const float* __restrict__ w0, const float* __restrict__ w1,
    const float* __restrict__ w2, const float* __restrict__ w3,
    const float* __restrict__ gru_w, const float* __restrict__ gru_b,
    const float* __restrict__ gru_const,
    const float* __restrict__ rel_embed)
{
    int bx = blockIdx.x;
    int tid = threadIdx.x;

    if (bx < PREP_CX) {
        int i = (bx * 256 + tid) * 4;
        float4 v = *(const float4*)&hidden[i];
        uint32_t h01, l01, h23, l23;
        splith2(v.x, v.y, h01, l01);
        splith2(v.z, v.w, h23, l23);
        *(uint2*)&g_xhi[i] = make_uint2(h01, h23);
        *(uint2*)&g_xlo[i] = make_uint2(l01, l23);
        return;
    }
    bx -= PREP_CX;
    if (bx < PREP_CW) {
        int i = (bx * 256 + tid) * 4;
        int sel = i >> 20;
        const float* src = sel==0 ? w0 : sel==1 ? w1 : sel==2 ? w2 : w3;
        float4 v = *(const float4*)&src[i & ((1<<20)-1)];
        uint32_t h01, l01, h23, l23;
        splith2(v.x, v.y, h01, l01);
        splith2(v.z, v.w, h23, l23);
        *(uint2*)&g_whi[i] = make_uint2(h01, h23);
        *(uint2*)&g_wlo[i] = make_uint2(l01, l23);
        return;
    }
    bx -= PREP_CW;
    if (bx < PREP_GT) {
        __shared__ float sw[8*DD];
        __shared__ float sb[8];
        __shared__ float scs[HH];
        for (int i = tid; i < 8*DD; i += 256) sw[i] = gru_w[i];
        if (tid < 8)  sb[tid] = gru_b[tid];
        if (tid < HH) scs[tid] = gru_const[tid];
        __syncthreads();

        int i = bx * 256 + tid;       // 0 .. 65535, full coverage now
        int h  = i % HH;
        int bt = i / HH;
        const float* x = hidden + (size_t)bt*EE + h*DD;
        float p[8];
        #pragma unroll
        for (int j = 0; j < 8; j++) p[j] = sb[j];
        #pragma unroll
        for (int d = 0; d < DD; d += 4) {
            float4 xv = *(const float4*)&x[d];
            #pragma unroll
            for (int j = 0; j < 8; j++) {
                p[j] += xv.x*sw[j*DD+d] + xv.y*sw[j*DD+d+1]
                      + xv.z*sw[j*DD+d+2] + xv.w*sw[j*DD+d+3];
            }
        }
        float pa = p[0]+p[1]+p[2]+p[3];
        float pb = p[4]+p[5]+p[6]+p[7];
        float ga = 1.0f/(1.0f + __expf(-pa));
        float gb = 1.0f/(1.0f + __expf(-pb));
        float gout = ga*(gb*scs[h] - 1.0f) + 2.0f;
        int b = bt / TT, t = bt % TT;
        g_gate[(b*HH + h)*TT + t] = gout;
        return;
    }
    bx -= PREP_GT;
    {
        int idx = bx * 256 + tid;
        if (idx >= BIAS_LEN) return;
        int delta = idx - (TT - 1);
        const int nb = 160;
        const int max_exact = 80;
        int rb = (delta > 0) ? nb : 0;
        int rel = abs(delta);
        int v;
        if (rel < max_exact) {
            v = rel;
        } else {
            float rf = (float)(rel < 1 ? 1 : rel);
            float large = logf(rf * (1.0f/80.0f)) * (float)(80.0 / 2.302585092994045684);
            int li = (int)((float)max_exact + large);
            v = li < (nb - 1) ? li : (nb - 1);
        }
        int bucket = rb + v;
        #pragma unroll
        for (int h = 0; h < HH; h++)
            g_bias[idx*HH + h] = rel_embed[bucket*HH + h];
    }
}

// ===========================================================================
// HMMA GEMM, fp16 3-pass hi/lo, cp.async 2-stage, KC=32.
// sel 0: q -> fp16 hi/lo (scaled).  sel 1/2: k/v -> fp16 hi only.
// sel 3: dense fp32 out (A = ctx hi/lo).
// ===========================================================================
#define KC 32
#define SPITCH 40
#define ARR (128*SPITCH)
#define STG (4*ARR)
#define GEMM_SMEM (2*STG*2)

__global__ __launch_bounds__(256, 2) void hmma_gemm_kernel(
    const float* __restrict__ b0in, const float* __restrict__ b1in,
    const float* __restrict__ b2in, const float* __restrict__ b3in,
    float* __restrict__ dense_out, int sel_base)
{
    extern __shared__ __half sh[];
    int tid = threadIdx.x;
    int sel = sel_base + blockIdx.z;
    int m0 = blockIdx.y * 128, n0 = blockIdx.x * 128;

    const __half* Ahi = (sel < 3) ? g_xhi : g_chi;
    const __half* Alo = (sel < 3) ? g_xlo : g_clo;
    const __half* Bhi = g_whi + ((size_t)sel << 20);
    const __half* Blo = g_wlo + ((size_t)sel << 20);
    const float* bias = sel==0 ? b0in : sel==1 ? b1in : sel==2 ? b2in : b3in;

    int wid = tid >> 5, lane = tid & 31;
    int warp_m = wid >> 2, warp_n = wid & 3;
    int gID = lane >> 2, tig = lane & 3;
    uint32_t sb = smem_u32(sh);

    int cp_arr[8], cp_r[8], cp_c8[8];
    #pragma unroll
    for (int j = 0; j < 8; j++) {
        int idx = tid + j*256;
        cp_arr[j] = idx >> 9;
        int c = idx & 511;
        cp_r[j] = c >> 2;
        cp_c8[j] = (c & 3) * 8;
    }

    float acc[4][4][4];
    #pragma unroll
    for (int mf = 0; mf < 4; mf++)
        #pragma unroll
        for (int nf = 0; nf < 4; nf++)
            #pragma unroll
            for (int c = 0; c < 4; c++) acc[mf][nf][c] = 0.0f;

    const int NK = EE / KC;

    auto prefetch = [&](int kt, int stage) {
        int k0 = kt * KC;
        uint32_t stg = sb + (uint32_t)stage*STG*2;
        #pragma unroll
        for (int j = 0; j < 8; j++) {
            int a = cp_arr[j], r = cp_r[j], c8 = cp_c8[j];
            const __half* src =
                (a == 0) ? (Ahi + (size_t)(m0+r)*EE + k0 + c8) :
                (a == 1) ? (Alo + (size_t)(m0+r)*EE + k0 + c8) :
                (a == 2) ? (Bhi + (size_t)(n0+r)*EE + k0 + c8) :
                           (Blo + (size_t)(n0+r)*EE + k0 + c8);
            cp16(stg + (uint32_t)(a*ARR + r*SPITCH + c8)*2, src);
        }
    };

    prefetch(0, 0);
    CP_COMMIT();

    for (int kt = 0; kt < NK; kt++) {
        int cur = kt & 1;
        if (kt + 1 < NK) { prefetch(kt+1, cur^1); CP_COMMIT(); CP_WAIT1(); }
        else             { CP_WAIT0(); }
        __syncthreads();

        const __half* s = sh + cur*STG;
        #pragma unroll
        for (int ks = 0; ks < KC/16; ks++) {
            int kc = ks*16 + 2*tig;
            uint32_t bh[4][2], bl[4][2];
            #pragma unroll
            for (int nf = 0; nf < 4; nf++) {
                int n = warp_n*32 + nf*8 + gID;
                bh[nf][0] = *(const uint32_t*)&s[2*ARR + n*SPITCH + kc];
                bh[nf][1] = *(const uint32_t*)&s[2*ARR + n*SPITCH + kc + 8];
                bl[nf][0] = *(const uint32_t*)&s[3*ARR + n*SPITCH + kc];
                bl[nf][1] = *(const uint32_t*)&s[3*ARR + n*SPITCH + kc + 8];
            }
            #pragma unroll
            for (int mf = 0; mf < 4; mf++) {
                int r = warp_m*64 + mf*16 + gID;
                uint32_t ah0 = *(const uint32_t*)&s[r*SPITCH + kc];
                uint32_t ah1 = *(const uint32_t*)&s[(r+8)*SPITCH + kc];
                uint32_t ah2 = *(const uint32_t*)&s[r*SPITCH + kc + 8];
                uint32_t ah3 = *(const uint32_t*)&s[(r+8)*SPITCH + kc + 8];
                uint32_t al0 = *(const uint32_t*)&s[ARR + r*SPITCH + kc];
                uint32_t al1 = *(const uint32_t*)&s[ARR + (r+8)*SPITCH + kc];
                uint32_t al2 = *(const uint32_t*)&s[ARR + r*SPITCH + kc + 8];
                uint32_t al3 = *(const uint32_t*)&s[ARR + (r+8)*SPITCH + kc + 8];
                #pragma unroll
                for (int nf = 0; nf < 4; nf++) {
                    hmma16816(acc[mf][nf], ah0, ah1, ah2, ah3, bh[nf][0], bh[nf][1]);
                    hmma16816(acc[mf][nf], ah0, ah1, ah2, ah3, bl[nf][0], bl[nf][1]);
                    hmma16816(acc[mf][nf], al0, al1, al2, al3, bh[nf][0], bh[nf][1]);
                }
            }
        }
        __syncthreads();
    }

    float scale = (sel == 0) ? 0.125f : 1.0f;
    #pragma unroll
    for (int mf = 0; mf < 4; mf++) {
        int m = m0 + warp_m*64 + mf*16 + gID;
        #pragma unroll
        for (int nf = 0; nf < 4; nf++) {
            int n = n0 + warp_n*32 + nf*8 + 2*tig;
            float bx = bias[n], by = bias[n+1];
            float v0 = (acc[mf][nf][0] + bx)*scale, v1 = (acc[mf][nf][1] + by)*scale;
            float v2 = (acc[mf][nf][2] + bx)*scale, v3 = (acc[mf][nf][3] + by)*scale;
            if (sel < 3) {
                int h = n >> 6, d = n & 63;
                int b1 = m >> 11, t1 = m & (TT-1);
                int m2 = m + 8;
                int b2 = m2 >> 11, t2 = m2 & (TT-1);
                size_t o1 = (((size_t)(b1*HH + h))*TT + t1)*DD + d;
                size_t o2 = (((size_t)(b2*HH + h))*TT + t2)*DD + d;
                if (sel == 0) {
                    uint32_t h01, l01, h23, l23;
                    splith2(v0, v1, h01, l01);
                    splith2(v2, v3, h23, l23);
                    *(uint32_t*)&g_qhi[o1] = h01;
                    *(uint32_t*)&g_qhi[o2] = h23;
                    *(uint32_t*)&g_qlo[o1] = l01;
                    *(uint32_t*)&g_qlo[o2] = l23;
                } else {
                    __half* dst = (sel == 1) ? g_kh : g_vh;
                    *(uint32_t*)&dst[o1] = packh2(v0, v1);
                    *(uint32_t*)&dst[o2] = packh2(v2, v3);
                }
            } else {
                *(float2*)&dense_out[(size_t)m*EE + n] = make_float2(v0, v1);
                *(float2*)&dense_out[(size_t)(m+8)*EE + n] = make_float2(v2, v3);
            }
        }
    }
}

// ===========================================================================
// HMMA flash attention, fp16: QK 2-pass (q exact, k fp16), PV 1-pass,
// online-max softmax. cp.async 2-stage, KV chunk 64.
// ===========================================================================
#define AT_KP 72
#define AT_TILE (64*AT_KP)
#define AT_STG (2*AT_TILE)             // Kh + Vh per stage
#define ATTN_SMEM (2*AT_STG*2 + 2*192*4)

__global__ __launch_bounds__(256, 2) void attn_mma_kernel()
{
    extern __shared__ __half ash[];
    float* bias_s = (float*)(ash + 2*AT_STG);    // [2][192]

    int tid = threadIdx.x;
    int wid = tid >> 5, lane = tid & 31;
    int gID = lane >> 2, tig = lane & 3;
    int bh = blockIdx.y;
    int b = bh >> 4, h = bh & 15;
    int t0 = blockIdx.x * 128;

    const __half* qh = g_qhi + ((size_t)bh*TT + t0)*DD;
    const __half* ql = g_qlo + ((size_t)bh*TT + t0)*DD;
    const __half* kh = g_kh + (size_t)bh*TT*DD;
    const __half* vh = g_vh + (size_t)bh*TT*DD;

    uint32_t qah[4][4], qal[4][4];
    int qr0 = wid*16 + gID;
    #pragma unroll
    for (int ks = 0; ks < 4; ks++) {
        qah[ks][0] = *(const uint32_t*)&qh[(size_t)qr0*DD + ks*16 + 2*tig];
        qah[ks][1] = *(const uint32_t*)&qh[(size_t)(qr0+8)*DD + ks*16 + 2*tig];
        qah[ks][2] = *(const uint32_t*)&qh[(size_t)qr0*DD + ks*16 + 8 + 2*tig];
        qah[ks][3] = *(const uint32_t*)&qh[(size_t)(qr0+8)*DD + ks*16 + 8 + 2*tig];
        qal[ks][0] = *(const uint32_t*)&ql[(size_t)qr0*DD + ks*16 + 2*tig];
        qal[ks][1] = *(const uint32_t*)&ql[(size_t)(qr0+8)*DD + ks*16 + 2*tig];
        qal[ks][2] = *(const uint32_t*)&ql[(size_t)qr0*DD + ks*16 + 8 + 2*tig];
        qal[ks][3] = *(const uint32_t*)&ql[(size_t)(qr0+8)*DD + ks*16 + 8 + 2*tig];
    }
    float g0_ = g_gate[(size_t)bh*TT + t0 + wid*16 + gID];
    float g1_ = g_gate[(size_t)bh*TT + t0 + wid*16 + gID + 8];

    float m0 = -1e30f, m1 = -1e30f, l0 = 0.0f, l1 = 0.0f;
    float oa[8][4];
    #pragma unroll
    for (int nf = 0; nf < 8; nf++)
        #pragma unroll
        for (int c = 0; c < 4; c++) oa[nf][c] = 0.0f;

    uint32_t sb = smem_u32(ash);

    auto loadKV = [&](int s0, int stage) {
        uint32_t stg = sb + (uint32_t)stage*AT_STG*2;
        #pragma unroll
        for (int j = 0; j < 4; j++) {
            int idx = tid + j*256;
            int a = idx >> 9;
            int c = idx & 511;
            int r = c >> 3, c8 = (c & 7)*8;
            size_t go = (size_t)(s0+r)*DD + c8;
            const __half* src = (a==0) ? kh+go : vh+go;
            cp16(stg + (uint32_t)(a*AT_TILE + r*AT_KP + c8)*2, src);
        }
    };

    const int NC = TT/64;
    loadKV(0, 0);
    CP_COMMIT();

    for (int ch = 0; ch < NC; ch++) {
        int cur = ch & 1;
        int s0 = ch * 64;
        if (ch + 1 < NC) { loadKV(s0 + 64, cur^1); CP_COMMIT(); CP_WAIT1(); }
        else             { CP_WAIT0(); }
        if (tid < 191)
            bias_s[cur*192 + tid] = g_bias[(size_t)(s0 - t0 - 127 + tid + TT - 1)*HH + h];
        __syncthreads();

        uint32_t kh_b = sb + (uint32_t)(cur*AT_STG)*2;
        uint32_t vh_b = kh_b + AT_TILE*2;
        const float* bw = bias_s + cur*192;

        // ---- S = Q K^T, 2-pass (q exact vs fp16 k)
        float sc[8][4];
        #pragma unroll
        for (int nf = 0; nf < 8; nf++)
            #pragma unroll
            for (int c = 0; c < 4; c++) sc[nf][c] = 0.0f;

        #pragma unroll
        for (int ks = 0; ks < 4; ks++) {
            #pragma unroll
            for (int np = 0; np < 4; np++) {
                uint32_t rowoff = (((np*16 + ((lane>>4)<<3) + (lane&7))*AT_KP) + ks*16 + (((lane>>3)&1)<<3))*2;
                uint32_t rh0, rh1, rh2, rh3;
                asm volatile("ldmatrix.sync.aligned.m8n8.x4.shared.b16 {%0,%1,%2,%3}, [%4];"
                             : "=r"(rh0), "=r"(rh1), "=r"(rh2), "=r"(rh3) : "r"(kh_b + rowoff));
                hmma16816(sc[2*np],   qah[ks][0], qah[ks][1], qah[ks][2], qah[ks][3], rh0, rh1);
                hmma16816(sc[2*np],   qal[ks][0], qal[ks][1], qal[ks][2], qal[ks][3], rh0, rh1);
                hmma16816(sc[2*np+1], qah[ks][0], qah[ks][1], qah[ks][2], qah[ks][3], rh2, rh3);
                hmma16816(sc[2*np+1], qal[ks][0], qal[ks][1], qal[ks][2], qal[ks][3], rh2, rh3);
            }
        }

        // ---- bias + online-max softmax
        float mx0 = -1e30f, mx1 = -1e30f;
        #pragma unroll
        for (int nf = 0; nf < 8; nf++) {
            int u = nf*8 + 2*tig - (wid*16 + gID) + 127;
            sc[nf][0] = fmaf(g0_, bw[u],   sc[nf][0]);
            sc[nf][1] = fmaf(g0_, bw[u+1], sc[nf][1]);
            sc[nf][2] = fmaf(g1_, bw[u-8], sc[nf][2]);
            sc[nf][3] = fmaf(g1_, bw[u-7], sc[nf][3]);
            mx0 = fmaxf(mx0, fmaxf(sc[nf][0], sc[nf][1]));
            mx1 = fmaxf(mx1, fmaxf(sc[nf][2], sc[nf][3]));
        }
        mx0 = fmaxf(mx0, __shfl_xor_sync(0xffffffffu, mx0, 1));
        mx0 = fmaxf(mx0, __shfl_xor_sync(0xffffffffu, mx0, 2));
        mx1 = fmaxf(mx1, __shfl_xor_sync(0xffffffffu, mx1, 1));
        mx1 = fmaxf(mx1, __shfl_xor_sync(0xffffffffu, mx1, 2));

        float mn0 = fmaxf(m0, mx0), mn1 = fmaxf(m1, mx1);
        float al0 = fexp(m0 - mn0), al1 = fexp(m1 - mn1);
        l0 *= al0;  l1 *= al1;
        #pragma unroll
        for (int nf = 0; nf < 8; nf++) {
            sc[nf][0] = fexp(sc[nf][0] - mn0); l0 += sc[nf][0];
            sc[nf][1] = fexp(sc[nf][1] - mn0); l0 += sc[nf][1];
            sc[nf][2] = fexp(sc[nf][2] - mn1); l1 += sc[nf][2];
            sc[nf][3] = fexp(sc[nf][3] - mn1); l1 += sc[nf][3];
        }
        m0 = mn0;  m1 = mn1;
        #pragma unroll
        for (int nf = 0; nf < 8; nf++) {
            oa[nf][0] *= al0; oa[nf][1] *= al0;
            oa[nf][2] *= al1; oa[nf][3] *= al1;
        }

        // ---- O += P V, 1-pass fp16 (P in (0,1])
        #pragma unroll
        for (int ksp = 0; ksp < 4; ksp++) {
            uint32_t pa0 = packh2(sc[2*ksp][0],   sc[2*ksp][1]);
            uint32_t pa1 = packh2(sc[2*ksp][2],   sc[2*ksp][3]);
            uint32_t pa2 = packh2(sc[2*ksp+1][0], sc[2*ksp+1][1]);
            uint32_t pa3 = packh2(sc[2*ksp+1][2], sc[2*ksp+1][3]);
            #pragma unroll
            for (int np = 0; np < 4; np++) {
                uint32_t rowoff = (((16*ksp + (lane&15))*AT_KP) + np*16 + ((lane>>4)<<3))*2;
                uint32_t rh0, rh1, rh2, rh3;
                asm volatile("ldmatrix.sync.aligned.m8n8.x4.trans.shared.b16 {%0,%1,%2,%3}, [%4];"
                             : "=r"(rh0), "=r"(rh1), "=r"(rh2), "=r"(rh3) : "r"(vh_b + rowoff));
                hmma16816(oa[2*np],   pa0, pa1, pa2, pa3, rh0, rh1);
                hmma16816(oa[2*np+1], pa0, pa1, pa2, pa3, rh2, rh3);
            }
        }
        __syncthreads();
    }

    // reduce partial l across tig lanes, normalize, write ctx fp16 hi/lo
    l0 += __shfl_xor_sync(0xffffffffu, l0, 1);
    l0 += __shfl_xor_sync(0xffffffffu, l0, 2);
    l1 += __shfl_xor_sync(0xffffffffu, l1, 1);
    l1 += __shfl_xor_sync(0xffffffffu, l1, 2);
    float inv0 = 1.0f / l0, inv1 = 1.0f / l1;
    int t = t0 + wid*16 + gID;
    #pragma unroll
    for (int nf = 0; nf < 8; nf++) {
        int d = nf*8 + 2*tig;
        uint32_t h0, l0p, h1, l1p;
        splith2(oa[nf][0]*inv0, oa[nf][1]*inv0, h0, l0p);
        splith2(oa[nf][2]*inv1, oa[nf][3]*inv1, h1, l1p);
        size_t o0 = ((size_t)(b*TT + t))*EE + h*DD + d;
        size_t o1 = ((size_t)(b*TT + t + 8))*EE + h*DD + d;
        *(uint32_t*)&g_chi[o0] = h0;
        *(uint32_t*)&g_chi[o1] = h1;
        *(uint32_t*)&g_clo[o0] = l0p;
        *(uint32_t*)&g_clo[o1] = l1p;
    }
}

// ---------------------------------------------------------------------------
extern "C" void kernel_launch(void* const* d_in, const int* in_sizes, int n_in,
                              void* d_out, int out_size)
{
    const float* hidden    = (const float*)d_in[0];
    const float* q_w       = (const float*)d_in[1];
    const float* q_b       = (const float*)d_in[2];
    const float* k_w       = (const float*)d_in[3];
    const float* k_b       = (const float*)d_in[4];
    const float* v_w       = (const float*)d_in[5];
    const float* v_b       = (const float*)d_in[6];
    const float* out_w     = (const float*)d_in[7];
    const float* out_b     = (const float*)d_in[8];
    const float* rel_embed = (const float*)d_in[9];
    const float* gru_const = (const float*)d_in[10];
    const float* gru_w     = (const float*)d_in[11];
    const float* gru_b     = (const float*)d_in[12];
    float* out = (float*)d_out;

    prep_kernel<<<PREP_BLOCKS, 256>>>(hidden, q_w, k_w, v_w, out_w,
                                      gru_w, gru_b, gru_const, rel_embed);

    cudaFuncSetAttribute(hmma_gemm_kernel, cudaFuncAttributeMaxDynamicSharedMemorySize, GEMM_SMEM);
    hmma_gemm_kernel<<<dim3(EE/128, BT/128, 3), 256, GEMM_SMEM>>>(q_b, k_b, v_b, out_b, out, 0);

    cudaFuncSetAttribute(attn_mma_kernel, cudaFuncAttributeMaxDynamicSharedMemorySize, ATTN_SMEM);
    attn_mma_kernel<<<dim3(TT/128, BB*HH), 256, ATTN_SMEM>>>();

    hmma_gemm_kernel<<<dim3(EE/128, BT/128, 1), 256, GEMM_SMEM>>>(q_b, k_b, v_b, out_b, out, 3);
}

// round 14
// speedup vs baseline: 3.8749x; 1.1744x over previous
#include <cuda_runtime.h>
#include <cuda_fp16.h>
#include <math.h>
#include <stdint.h>

#define BB 2
#define TT 2048
#define EE 1024
#define HH 16
#define DD 64
#define BT (BB*TT)            // 4096
#define BIAS_LEN (2*TT-1)     // 4095

// Scratch (device globals)
__device__ float g_gate[BB*HH*TT];
__device__ float g_bias[BIAS_LEN*HH];
__device__ __half g_qhi[BB*HH*TT*DD], g_qlo[BB*HH*TT*DD];
__device__ __half g_kh[BB*HH*TT*DD];
__device__ __half g_vh[BB*HH*TT*DD];
__device__ __half g_xhi[BT*EE], g_xlo[BT*EE];
__device__ __half g_whi[4*EE*EE];
__device__ __half g_chi[BT*EE], g_clo[BT*EE];

// ===========================================================================
// helpers
// ===========================================================================
__device__ __forceinline__ uint32_t smem_u32(const void* p) {
    uint32_t a;
    asm("{ .reg .u64 t; cvta.to.shared.u64 t, %1; cvt.u32.u64 %0, t; }" : "=r"(a) : "l"(p));
    return a;
}
__device__ __forceinline__ void cp16(uint32_t dst, const void* src) {
    asm volatile("cp.async.ca.shared.global [%0], [%1], 16;" :: "r"(dst), "l"(src));
}
#define CP_COMMIT() asm volatile("cp.async.commit_group;" ::: "memory")
#define CP_WAIT1()  asm volatile("cp.async.wait_group 1;" ::: "memory")
#define CP_WAIT0()  asm volatile("cp.async.wait_group 0;" ::: "memory")

__device__ __forceinline__ void hmma16816(float c[4],
                                          uint32_t a0, uint32_t a1, uint32_t a2, uint32_t a3,
                                          uint32_t b0, uint32_t b1)
{
    asm volatile(
        "mma.sync.aligned.m16n8k16.row.col.f32.f16.f16.f32 "
        "{%0,%1,%2,%3}, {%4,%5,%6,%7}, {%8,%9}, {%0,%1,%2,%3};"
        : "+f"(c[0]), "+f"(c[1]), "+f"(c[2]), "+f"(c[3])
        : "r"(a0), "r"(a1), "r"(a2), "r"(a3), "r"(b0), "r"(b1));
}
// FMA-pipe exp (no MUFU); args <= 0 (online-max softmax)
__device__ __forceinline__ float fexp(float x) {
    x = fmaxf(x, -80.0f);
    float z = fmaf(x, 1.4426950408889634f, 12582912.0f);
    int n = __float_as_int(z) - 0x4B400000;
    float r = z - 12582912.0f;
    float f = fmaf(r, -0.6931471805599453f, x);
    float p = fmaf(f, 0.008333333f, 0.041666666f);
    p = fmaf(f, p, 0.16666667f);
    p = fmaf(f, p, 0.5f);
    p = fmaf(f, p, 1.0f);
    p = fmaf(f, p, 1.0f);
    return __int_as_float(__float_as_int(p) + (n << 23));
}
__device__ __forceinline__ uint32_t packh2(float a, float b) {
    __half2 t = __floats2half2_rn(a, b);
    return *(uint32_t*)&t;
}
__device__ __forceinline__ void splith2(float a, float b, uint32_t& hi, uint32_t& lo) {
    __half ha = __float2half_rn(a), hb = __float2half_rn(b);
    __half2 t{ha, hb};
    hi = *(uint32_t*)&t;
    lo = packh2(a - __half2float(ha), b - __half2float(hb));
}

// ===========================================================================
// Fused prep: conv_x | conv_w (hi only) | gate | bias_table
// ===========================================================================
#define PREP_CX 4096
#define PREP_CW 4096
#define PREP_GT 256
#define PREP_BT 16
#define PREP_BLOCKS (PREP_CX + PREP_CW + PREP_GT + PREP_BT)

__global__ __launch_bounds__(256) void prep_kernel(
    const float* __restrict__ hidden,
    const float* __restrict__ w0, const float* __restrict__ w1,
    const float* __restrict__ w2, const float* __restrict__ w3,
    const float* __restrict__ gru_w, const float* __restrict__ gru_b,
    const float* __restrict__ gru_const,
    const float* __restrict__ rel_embed)
{
    int bx = blockIdx.x;
    int tid = threadIdx.x;

    if (bx < PREP_CX) {
        int i = (bx * 256 + tid) * 4;
        float4 v = *(const float4*)&hidden[i];
        uint32_t h01, l01, h23, l23;
        splith2(v.x, v.y, h01, l01);
        splith2(v.z, v.w, h23, l23);
        *(uint2*)&g_xhi[i] = make_uint2(h01, h23);
        *(uint2*)&g_xlo[i] = make_uint2(l01, l23);
        return;
    }
    bx -= PREP_CX;
    if (bx < PREP_CW) {
        int i = (bx * 256 + tid) * 4;
        int sel = i >> 20;
        const float* src = sel==0 ? w0 : sel==1 ? w1 : sel==2 ? w2 : w3;
        float4 v = *(const float4*)&src[i & ((1<<20)-1)];
        uint32_t h01 = packh2(v.x, v.y);
        uint32_t h23 = packh2(v.z, v.w);
        *(uint2*)&g_whi[i] = make_uint2(h01, h23);
        return;
    }
    bx -= PREP_CW;
    if (bx < PREP_GT) {
        __shared__ float sw[8*DD];
        __shared__ float sb[8];
        __shared__ float scs[HH];
        for (int i = tid; i < 8*DD; i += 256) sw[i] = gru_w[i];
        if (tid < 8)  sb[tid] = gru_b[tid];
        if (tid < HH) scs[tid] = gru_const[tid];
        __syncthreads();

        int i = bx * 256 + tid;       // full 65536 coverage
        int h  = i % HH;
        int bt = i / HH;
        const float* x = hidden + (size_t)bt*EE + h*DD;
        float p[8];
        #pragma unroll
        for (int j = 0; j < 8; j++) p[j] = sb[j];
        #pragma unroll
        for (int d = 0; d < DD; d += 4) {
            float4 xv = *(const float4*)&x[d];
            #pragma unroll
            for (int j = 0; j < 8; j++) {
                p[j] += xv.x*sw[j*DD+d] + xv.y*sw[j*DD+d+1]
                      + xv.z*sw[j*DD+d+2] + xv.w*sw[j*DD+d+3];
            }
        }
        float pa = p[0]+p[1]+p[2]+p[3];
        float pb = p[4]+p[5]+p[6]+p[7];
        float ga = 1.0f/(1.0f + __expf(-pa));
        float gb = 1.0f/(1.0f + __expf(-pb));
        float gout = ga*(gb*scs[h] - 1.0f) + 2.0f;
        int b = bt / TT, t = bt % TT;
        g_gate[(b*HH + h)*TT + t] = gout;
        return;
    }
    bx -= PREP_GT;
    {
        int idx = bx * 256 + tid;
        if (idx >= BIAS_LEN) return;
        int delta = idx - (TT - 1);
        const int nb = 160;
        const int max_exact = 80;
        int rb = (delta > 0) ? nb : 0;
        int rel = abs(delta);
        int v;
        if (rel < max_exact) {
            v = rel;
        } else {
            float rf = (float)(rel < 1 ? 1 : rel);
            float large = logf(rf * (1.0f/80.0f)) * (float)(80.0 / 2.302585092994045684);
            int li = (int)((float)max_exact + large);
            v = li < (nb - 1) ? li : (nb - 1);
        }
        int bucket = rb + v;
        #pragma unroll
        for (int h = 0; h < HH; h++)
            g_bias[idx*HH + h] = rel_embed[bucket*HH + h];
    }
}

// ===========================================================================
// HMMA GEMM, fp16 2-pass (A hi/lo exact, W fp16), cp.async 2-stage, KC=32.
// smem arrays per stage: 0=Ahi, 1=Alo, 2=Whi.
// sel 0: q -> fp16 hi/lo (scaled).  sel 1/2: k/v -> fp16.  sel 3: fp32 out.
// ===========================================================================
#define KC 32
#define SPITCH 40
#define ARR (128*SPITCH)
#define STG (3*ARR)
#define GEMM_SMEM (2*STG*2)

__global__ __launch_bounds__(256, 2) void hmma_gemm_kernel(
    const float* __restrict__ b0in, const float* __restrict__ b1in,
    const float* __restrict__ b2in, const float* __restrict__ b3in,
    float* __restrict__ dense_out, int sel_base)
{
    extern __shared__ __half sh[];
    int tid = threadIdx.x;
    int sel = sel_base + blockIdx.z;
    int m0 = blockIdx.y * 128, n0 = blockIdx.x * 128;

    const __half* Ahi = (sel < 3) ? g_xhi : g_chi;
    const __half* Alo = (sel < 3) ? g_xlo : g_clo;
    const __half* Whi = g_whi + ((size_t)sel << 20);
    const float* bias = sel==0 ? b0in : sel==1 ? b1in : sel==2 ? b2in : b3in;

    int wid = tid >> 5, lane = tid & 31;
    int warp_m = wid >> 2, warp_n = wid & 3;
    int gID = lane >> 2, tig = lane & 3;
    uint32_t sb = smem_u32(sh);

    // 3 arrays x 512 slots = 1536 cp slots, 6 per thread
    int cp_arr[6], cp_r[6], cp_c8[6];
    #pragma unroll
    for (int j = 0; j < 6; j++) {
        int idx = tid + j*256;
        cp_arr[j] = idx >> 9;
        int c = idx & 511;
        cp_r[j] = c >> 2;
        cp_c8[j] = (c & 3) * 8;
    }

    float acc[4][4][4];
    #pragma unroll
    for (int mf = 0; mf < 4; mf++)
        #pragma unroll
        for (int nf = 0; nf < 4; nf++)
            #pragma unroll
            for (int c = 0; c < 4; c++) acc[mf][nf][c] = 0.0f;

    const int NK = EE / KC;

    auto prefetch = [&](int kt, int stage) {
        int k0 = kt * KC;
        uint32_t stg = sb + (uint32_t)stage*STG*2;
        #pragma unroll
        for (int j = 0; j < 6; j++) {
            int a = cp_arr[j], r = cp_r[j], c8 = cp_c8[j];
            const __half* src =
                (a == 0) ? (Ahi + (size_t)(m0+r)*EE + k0 + c8) :
                (a == 1) ? (Alo + (size_t)(m0+r)*EE + k0 + c8) :
                           (Whi + (size_t)(n0+r)*EE + k0 + c8);
            cp16(stg + (uint32_t)(a*ARR + r*SPITCH + c8)*2, src);
        }
    };

    prefetch(0, 0);
    CP_COMMIT();

    for (int kt = 0; kt < NK; kt++) {
        int cur = kt & 1;
        if (kt + 1 < NK) { prefetch(kt+1, cur^1); CP_COMMIT(); CP_WAIT1(); }
        else             { CP_WAIT0(); }
        __syncthreads();

        const __half* s = sh + cur*STG;
        #pragma unroll
        for (int ks = 0; ks < KC/16; ks++) {
            int kc = ks*16 + 2*tig;
            uint32_t bh[4][2];
            #pragma unroll
            for (int nf = 0; nf < 4; nf++) {
                int n = warp_n*32 + nf*8 + gID;
                bh[nf][0] = *(const uint32_t*)&s[2*ARR + n*SPITCH + kc];
                bh[nf][1] = *(const uint32_t*)&s[2*ARR + n*SPITCH + kc + 8];
            }
            #pragma unroll
            for (int mf = 0; mf < 4; mf++) {
                int r = warp_m*64 + mf*16 + gID;
                uint32_t ah0 = *(const uint32_t*)&s[r*SPITCH + kc];
                uint32_t ah1 = *(const uint32_t*)&s[(r+8)*SPITCH + kc];
                uint32_t ah2 = *(const uint32_t*)&s[r*SPITCH + kc + 8];
                uint32_t ah3 = *(const uint32_t*)&s[(r+8)*SPITCH + kc + 8];
                uint32_t al0 = *(const uint32_t*)&s[ARR + r*SPITCH + kc];
                uint32_t al1 = *(const uint32_t*)&s[ARR + (r+8)*SPITCH + kc];
                uint32_t al2 = *(const uint32_t*)&s[ARR + r*SPITCH + kc + 8];
                uint32_t al3 = *(const uint32_t*)&s[ARR + (r+8)*SPITCH + kc + 8];
                #pragma unroll
                for (int nf = 0; nf < 4; nf++) {
                    hmma16816(acc[mf][nf], ah0, ah1, ah2, ah3, bh[nf][0], bh[nf][1]);
                    hmma16816(acc[mf][nf], al0, al1, al2, al3, bh[nf][0], bh[nf][1]);
                }
            }
        }
        __syncthreads();
    }

    float scale = (sel == 0) ? 0.125f : 1.0f;
    #pragma unroll
    for (int mf = 0; mf < 4; mf++) {
        int m = m0 + warp_m*64 + mf*16 + gID;
        #pragma unroll
        for (int nf = 0; nf < 4; nf++) {
            int n = n0 + warp_n*32 + nf*8 + 2*tig;
            float bx = bias[n], by = bias[n+1];
            float v0 = (acc[mf][nf][0] + bx)*scale, v1 = (acc[mf][nf][1] + by)*scale;
            float v2 = (acc[mf][nf][2] + bx)*scale, v3 = (acc[mf][nf][3] + by)*scale;
            if (sel < 3) {
                int h = n >> 6, d = n & 63;
                int b1 = m >> 11, t1 = m & (TT-1);
                int m2 = m + 8;
                int b2 = m2 >> 11, t2 = m2 & (TT-1);
                size_t o1 = (((size_t)(b1*HH + h))*TT + t1)*DD + d;
                size_t o2 = (((size_t)(b2*HH + h))*TT + t2)*DD + d;
                if (sel == 0) {
                    uint32_t h01, l01, h23, l23;
                    splith2(v0, v1, h01, l01);
                    splith2(v2, v3, h23, l23);
                    *(uint32_t*)&g_qhi[o1] = h01;
                    *(uint32_t*)&g_qhi[o2] = h23;
                    *(uint32_t*)&g_qlo[o1] = l01;
                    *(uint32_t*)&g_qlo[o2] = l23;
                } else {
                    __half* dst = (sel == 1) ? g_kh : g_vh;
                    *(uint32_t*)&dst[o1] = packh2(v0, v1);
                    *(uint32_t*)&dst[o2] = packh2(v2, v3);
                }
            } else {
                *(float2*)&dense_out[(size_t)m*EE + n] = make_float2(v0, v1);
                *(float2*)&dense_out[(size_t)(m+8)*EE + n] = make_float2(v2, v3);
            }
        }
    }
}

// ===========================================================================
// HMMA flash attention (R11 verbatim): QK 2-pass, PV 1-pass fp16,
// online-max softmax, cp.async 2-stage, KV chunk 64.
// ===========================================================================
#define AT_KP 72
#define AT_TILE (64*AT_KP)
#define AT_STG (2*AT_TILE)
#define ATTN_SMEM (2*AT_STG*2 + 2*192*4)

__global__ __launch_bounds__(256, 2) void attn_mma_kernel()
{
    extern __shared__ __half ash[];
    float* bias_s = (float*)(ash + 2*AT_STG);    // [2][192]

    int tid = threadIdx.x;
    int wid = tid >> 5, lane = tid & 31;
    int gID = lane >> 2, tig = lane & 3;
    int bh = blockIdx.y;
    int b = bh >> 4, h = bh & 15;
    int t0 = blockIdx.x * 128;

    const __half* qh = g_qhi + ((size_t)bh*TT + t0)*DD;
    const __half* ql = g_qlo + ((size_t)bh*TT + t0)*DD;
    const __half* kh = g_kh + (size_t)bh*TT*DD;
    const __half* vh = g_vh + (size_t)bh*TT*DD;

    uint32_t qah[4][4], qal[4][4];
    int qr0 = wid*16 + gID;
    #pragma unroll
    for (int ks = 0; ks < 4; ks++) {
        qah[ks][0] = *(const uint32_t*)&qh[(size_t)qr0*DD + ks*16 + 2*tig];
        qah[ks][1] = *(const uint32_t*)&qh[(size_t)(qr0+8)*DD + ks*16 + 2*tig];
        qah[ks][2] = *(const uint32_t*)&qh[(size_t)qr0*DD + ks*16 + 8 + 2*tig];
        qah[ks][3] = *(const uint32_t*)&qh[(size_t)(qr0+8)*DD + ks*16 + 8 + 2*tig];
        qal[ks][0] = *(const uint32_t*)&ql[(size_t)qr0*DD + ks*16 + 2*tig];
        qal[ks][1] = *(const uint32_t*)&ql[(size_t)(qr0+8)*DD + ks*16 + 2*tig];
        qal[ks][2] = *(const uint32_t*)&ql[(size_t)qr0*DD + ks*16 + 8 + 2*tig];
        qal[ks][3] = *(const uint32_t*)&ql[(size_t)(qr0+8)*DD + ks*16 + 8 + 2*tig];
    }
    float g0_ = g_gate[(size_t)bh*TT + t0 + wid*16 + gID];
    float g1_ = g_gate[(size_t)bh*TT + t0 + wid*16 + gID + 8];

    float m0 = -1e30f, m1 = -1e30f, l0 = 0.0f, l1 = 0.0f;
    float oa[8][4];
    #pragma unroll
    for (int nf = 0; nf < 8; nf++)
        #pragma unroll
        for (int c = 0; c < 4; c++) oa[nf][c] = 0.0f;

    uint32_t sb = smem_u32(ash);

    auto loadKV = [&](int s0, int stage) {
        uint32_t stg = sb + (uint32_t)stage*AT_STG*2;
        #pragma unroll
        for (int j = 0; j < 4; j++) {
            int idx = tid + j*256;
            int a = idx >> 9;
            int c = idx & 511;
            int r = c >> 3, c8 = (c & 7)*8;
            size_t go = (size_t)(s0+r)*DD + c8;
            const __half* src = (a==0) ? kh+go : vh+go;
            cp16(stg + (uint32_t)(a*AT_TILE + r*AT_KP + c8)*2, src);
        }
    };

    const int NC = TT/64;
    loadKV(0, 0);
    CP_COMMIT();

    for (int ch = 0; ch < NC; ch++) {
        int cur = ch & 1;
        int s0 = ch * 64;
        if (ch + 1 < NC) { loadKV(s0 + 64, cur^1); CP_COMMIT(); CP_WAIT1(); }
        else             { CP_WAIT0(); }
        if (tid < 191)
            bias_s[cur*192 + tid] = g_bias[(size_t)(s0 - t0 - 127 + tid + TT - 1)*HH + h];
        __syncthreads();

        uint32_t kh_b = sb + (uint32_t)(cur*AT_STG)*2;
        uint32_t vh_b = kh_b + AT_TILE*2;
        const float* bw = bias_s + cur*192;

        float sc[8][4];
        #pragma unroll
        for (int nf = 0; nf < 8; nf++)
            #pragma unroll
            for (int c = 0; c < 4; c++) sc[nf][c] = 0.0f;

        #pragma unroll
        for (int ks = 0; ks < 4; ks++) {
            #pragma unroll
            for (int np = 0; np < 4; np++) {
                uint32_t rowoff = (((np*16 + ((lane>>4)<<3) + (lane&7))*AT_KP) + ks*16 + (((lane>>3)&1)<<3))*2;
                uint32_t rh0, rh1, rh2, rh3;
                asm volatile("ldmatrix.sync.aligned.m8n8.x4.shared.b16 {%0,%1,%2,%3}, [%4];"
                             : "=r"(rh0), "=r"(rh1), "=r"(rh2), "=r"(rh3) : "r"(kh_b + rowoff));
                hmma16816(sc[2*np],   qah[ks][0], qah[ks][1], qah[ks][2], qah[ks][3], rh0, rh1);
                hmma16816(sc[2*np],   qal[ks][0], qal[ks][1], qal[ks][2], qal[ks][3], rh0, rh1);
                hmma16816(sc[2*np+1], qah[ks][0], qah[ks][1], qah[ks][2], qah[ks][3], rh2, rh3);
                hmma16816(sc[2*np+1], qal[ks][0], qal[ks][1], qal[ks][2], qal[ks][3], rh2, rh3);
            }
        }

        float mx0 = -1e30f, mx1 = -1e30f;
        #pragma unroll
        for (int nf = 0; nf < 8; nf++) {
            int u = nf*8 + 2*tig - (wid*16 + gID) + 127;
            sc[nf][0] = fmaf(g0_, bw[u],   sc[nf][0]);
            sc[nf][1] = fmaf(g0_, bw[u+1], sc[nf][1]);
            sc[nf][2] = fmaf(g1_, bw[u-8], sc[nf][2]);
            sc[nf][3] = fmaf(g1_, bw[u-7], sc[nf][3]);
            mx0 = fmaxf(mx0, fmaxf(sc[nf][0], sc[nf][1]));
            mx1 = fmaxf(mx1, fmaxf(sc[nf][2], sc[nf][3]));
        }
        mx0 = fmaxf(mx0, __shfl_xor_sync(0xffffffffu, mx0, 1));
        mx0 = fmaxf(mx0, __shfl_xor_sync(0xffffffffu, mx0, 2));
        mx1 = fmaxf(mx1, __shfl_xor_sync(0xffffffffu, mx1, 1));
        mx1 = fmaxf(mx1, __shfl_xor_sync(0xffffffffu, mx1, 2));

        float mn0 = fmaxf(m0, mx0), mn1 = fmaxf(m1, mx1);
        float al0 = fexp(m0 - mn0), al1 = fexp(m1 - mn1);
        l0 *= al0;  l1 *= al1;
        #pragma unroll
        for (int nf = 0; nf < 8; nf++) {
            sc[nf][0] = fexp(sc[nf][0] - mn0); l0 += sc[nf][0];
            sc[nf][1] = fexp(sc[nf][1] - mn0); l0 += sc[nf][1];
            sc[nf][2] = fexp(sc[nf][2] - mn1); l1 += sc[nf][2];
            sc[nf][3] = fexp(sc[nf][3] - mn1); l1 += sc[nf][3];
        }
        m0 = mn0;  m1 = mn1;
        #pragma unroll
        for (int nf = 0; nf < 8; nf++) {
            oa[nf][0] *= al0; oa[nf][1] *= al0;
            oa[nf][2] *= al1; oa[nf][3] *= al1;
        }

        #pragma unroll
        for (int ksp = 0; ksp < 4; ksp++) {
            uint32_t pa0 = packh2(sc[2*ksp][0],   sc[2*ksp][1]);
            uint32_t pa1 = packh2(sc[2*ksp][2],   sc[2*ksp][3]);
            uint32_t pa2 = packh2(sc[2*ksp+1][0], sc[2*ksp+1][1]);
            uint32_t pa3 = packh2(sc[2*ksp+1][2], sc[2*ksp+1][3]);
            #pragma unroll
            for (int np = 0; np < 4; np++) {
                uint32_t rowoff = (((16*ksp + (lane&15))*AT_KP) + np*16 + ((lane>>4)<<3))*2;
                uint32_t rh0, rh1, rh2, rh3;
                asm volatile("ldmatrix.sync.aligned.m8n8.x4.trans.shared.b16 {%0,%1,%2,%3}, [%4];"
                             : "=r"(rh0), "=r"(rh1), "=r"(rh2), "=r"(rh3) : "r"(vh_b + rowoff));
                hmma16816(oa[2*np],   pa0, pa1, pa2, pa3, rh0, rh1);
                hmma16816(oa[2*np+1], pa0, pa1, pa2, pa3, rh2, rh3);
            }
        }
        __syncthreads();
    }

    l0 += __shfl_xor_sync(0xffffffffu, l0, 1);
    l0 += __shfl_xor_sync(0xffffffffu, l0, 2);
    l1 += __shfl_xor_sync(0xffffffffu, l1, 1);
    l1 += __shfl_xor_sync(0xffffffffu, l1, 2);
    float inv0 = 1.0f / l0, inv1 = 1.0f / l1;
    int t = t0 + wid*16 + gID;
    #pragma unroll
    for (int nf = 0; nf < 8; nf++) {
        int d = nf*8 + 2*tig;
        uint32_t h0, l0p, h1, l1p;
        splith2(oa[nf][0]*inv0, oa[nf][1]*inv0, h0, l0p);
        splith2(oa[nf][2]*inv1, oa[nf][3]*inv1, h1, l1p);
        size_t o0 = ((size_t)(b*TT + t))*EE + h*DD + d;
        size_t o1 = ((size_t)(b*TT + t + 8))*EE + h*DD + d;
        *(uint32_t*)&g_chi[o0] = h0;
        *(uint32_t*)&g_chi[o1] = h1;
        *(uint32_t*)&g_clo[o0] = l0p;
        *(uint32_t*)&g_clo[o1] = l1p;
    }
}

// ---------------------------------------------------------------------------
extern "C" void kernel_launch(void* const* d_in, const int* in_sizes, int n_in,
                              void* d_out, int out_size)
{
    const float* hidden    = (const float*)d_in[0];
    const float* q_w       = (const float*)d_in[1];
    const float* q_b       = (const float*)d_in[2];
    const float* k_w       = (const float*)d_in[3];
    const float* k_b       = (const float*)d_in[4];
    const float* v_w       = (const float*)d_in[5];
    const float* v_b       = (const float*)d_in[6];
    const float* out_w     = (const float*)d_in[7];
    const float* out_b     = (const float*)d_in[8];
    const float* rel_embed = (const float*)d_in[9];
    const float* gru_const = (const float*)d_in[10];
    const float* gru_w     = (const float*)d_in[11];
    const float* gru_b     = (const float*)d_in[12];
    float* out = (float*)d_out;

    prep_kernel<<<PREP_BLOCKS, 256>>>(hidden, q_w, k_w, v_w, out_w,
                                      gru_w, gru_b, gru_const, rel_embed);

    cudaFuncSetAttribute(hmma_gemm_kernel, cudaFuncAttributeMaxDynamicSharedMemorySize, GEMM_SMEM);
    hmma_gemm_kernel<<<dim3(EE/128, BT/128, 3), 256, GEMM_SMEM>>>(q_b, k_b, v_b, out_b, out, 0);

    cudaFuncSetAttribute(attn_mma_kernel, cudaFuncAttributeMaxDynamicSharedMemorySize, ATTN_SMEM);
    attn_mma_kernel<<<dim3(TT/128, BB*HH), 256, ATTN_SMEM>>>();

    hmma_gemm_kernel<<<dim3(EE/128, BT/128, 1), 256, GEMM_SMEM>>>(q_b, k_b, v_b, out_b, out, 3);
}

// round 15
// speedup vs baseline: 4.0725x; 1.0510x over previous
#include <cuda_runtime.h>
#include <cuda_fp16.h>
#include <math.h>
#include <stdint.h>

#define BB 2
#define TT 2048
#define EE 1024
#define HH 16
#define DD 64
#define BT (BB*TT)            // 4096
#define BIAS_LEN (2*TT-1)     // 4095

// Scratch (device globals)
__device__ float g_gate[BB*HH*TT];
__device__ float g_bias[BIAS_LEN*HH];
__device__ __half g_qh[BB*HH*TT*DD];
__device__ __half g_kh[BB*HH*TT*DD];
__device__ __half g_vh[BB*HH*TT*DD];
__device__ __half g_xhi[BT*EE], g_xlo[BT*EE];
__device__ __half g_whi[4*EE*EE];
__device__ __half g_chi[BT*EE], g_clo[BT*EE];

// ===========================================================================
// helpers
// ===========================================================================
__device__ __forceinline__ uint32_t smem_u32(const void* p) {
    uint32_t a;
    asm("{ .reg .u64 t; cvta.to.shared.u64 t, %1; cvt.u32.u64 %0, t; }" : "=r"(a) : "l"(p));
    return a;
}
__device__ __forceinline__ void cp16(uint32_t dst, const void* src) {
    asm volatile("cp.async.ca.shared.global [%0], [%1], 16;" :: "r"(dst), "l"(src));
}
#define CP_COMMIT() asm volatile("cp.async.commit_group;" ::: "memory")
#define CP_WAIT2()  asm volatile("cp.async.wait_group 2;" ::: "memory")
#define CP_WAIT1()  asm volatile("cp.async.wait_group 1;" ::: "memory")
#define CP_WAIT0()  asm volatile("cp.async.wait_group 0;" ::: "memory")

__device__ __forceinline__ void hmma16816(float c[4],
                                          uint32_t a0, uint32_t a1, uint32_t a2, uint32_t a3,
                                          uint32_t b0, uint32_t b1)
{
    asm volatile(
        "mma.sync.aligned.m16n8k16.row.col.f32.f16.f16.f32 "
        "{%0,%1,%2,%3}, {%4,%5,%6,%7}, {%8,%9}, {%0,%1,%2,%3};"
        : "+f"(c[0]), "+f"(c[1]), "+f"(c[2]), "+f"(c[3])
        : "r"(a0), "r"(a1), "r"(a2), "r"(a3), "r"(b0), "r"(b1));
}
// FMA-pipe exp (no MUFU); args <= 0 (online-max softmax)
__device__ __forceinline__ float fexp(float x) {
    x = fmaxf(x, -80.0f);
    float z = fmaf(x, 1.4426950408889634f, 12582912.0f);
    int n = __float_as_int(z) - 0x4B400000;
    float r = z - 12582912.0f;
    float f = fmaf(r, -0.6931471805599453f, x);
    float p = fmaf(f, 0.008333333f, 0.041666666f);
    p = fmaf(f, p, 0.16666667f);
    p = fmaf(f, p, 0.5f);
    p = fmaf(f, p, 1.0f);
    p = fmaf(f, p, 1.0f);
    return __int_as_float(__float_as_int(p) + (n << 23));
}
__device__ __forceinline__ uint32_t packh2(float a, float b) {
    __half2 t = __floats2half2_rn(a, b);
    return *(uint32_t*)&t;
}
__device__ __forceinline__ void splith2(float a, float b, uint32_t& hi, uint32_t& lo) {
    __half ha = __float2half_rn(a), hb = __float2half_rn(b);
    __half2 t{ha, hb};
    hi = *(uint32_t*)&t;
    lo = packh2(a - __half2float(ha), b - __half2float(hb));
}

// ===========================================================================
// Fused prep: conv_x | conv_w (hi only) | gate | bias_table
// ===========================================================================
#define PREP_CX 4096
#define PREP_CW 4096
#define PREP_GT 256
#define PREP_BT 16
#define PREP_BLOCKS (PREP_CX + PREP_CW + PREP_GT + PREP_BT)

__global__ __launch_bounds__(256) void prep_kernel(
    const float* __restrict__ hidden,
    const float* __restrict__ w0, const float* __restrict__ w1,
    const float* __restrict__ w2, const float* __restrict__ w3,
    const float* __restrict__ gru_w, const float* __restrict__ gru_b,
    const float* __restrict__ gru_const,
    const float* __restrict__ rel_embed)
{
    int bx = blockIdx.x;
    int tid = threadIdx.x;

    if (bx < PREP_CX) {
        int i = (bx * 256 + tid) * 4;
        float4 v = *(const float4*)&hidden[i];
        uint32_t h01, l01, h23, l23;
        splith2(v.x, v.y, h01, l01);
        splith2(v.z, v.w, h23, l23);
        *(uint2*)&g_xhi[i] = make_uint2(h01, h23);
        *(uint2*)&g_xlo[i] = make_uint2(l01, l23);
        return;
    }
    bx -= PREP_CX;
    if (bx < PREP_CW) {
        int i = (bx * 256 + tid) * 4;
        int sel = i >> 20;
        const float* src = sel==0 ? w0 : sel==1 ? w1 : sel==2 ? w2 : w3;
        float4 v = *(const float4*)&src[i & ((1<<20)-1)];
        uint32_t h01 = packh2(v.x, v.y);
        uint32_t h23 = packh2(v.z, v.w);
        *(uint2*)&g_whi[i] = make_uint2(h01, h23);
        return;
    }
    bx -= PREP_CW;
    if (bx < PREP_GT) {
        __shared__ float sw[8*DD];
        __shared__ float sb[8];
        __shared__ float scs[HH];
        for (int i = tid; i < 8*DD; i += 256) sw[i] = gru_w[i];
        if (tid < 8)  sb[tid] = gru_b[tid];
        if (tid < HH) scs[tid] = gru_const[tid];
        __syncthreads();

        int i = bx * 256 + tid;       // full 65536 coverage
        int h  = i % HH;
        int bt = i / HH;
        const float* x = hidden + (size_t)bt*EE + h*DD;
        float p[8];
        #pragma unroll
        for (int j = 0; j < 8; j++) p[j] = sb[j];
        #pragma unroll
        for (int d = 0; d < DD; d += 4) {
            float4 xv = *(const float4*)&x[d];
            #pragma unroll
            for (int j = 0; j < 8; j++) {
                p[j] += xv.x*sw[j*DD+d] + xv.y*sw[j*DD+d+1]
                      + xv.z*sw[j*DD+d+2] + xv.w*sw[j*DD+d+3];
            }
        }
        float pa = p[0]+p[1]+p[2]+p[3];
        float pb = p[4]+p[5]+p[6]+p[7];
        float ga = 1.0f/(1.0f + __expf(-pa));
        float gb = 1.0f/(1.0f + __expf(-pb));
        float gout = ga*(gb*scs[h] - 1.0f) + 2.0f;
        int b = bt / TT, t = bt % TT;
        g_gate[(b*HH + h)*TT + t] = gout;
        return;
    }
    bx -= PREP_GT;
    {
        int idx = bx * 256 + tid;
        if (idx >= BIAS_LEN) return;
        int delta = idx - (TT - 1);
        const int nb = 160;
        const int max_exact = 80;
        int rb = (delta > 0) ? nb : 0;
        int rel = abs(delta);
        int v;
        if (rel < max_exact) {
            v = rel;
        } else {
            float rf = (float)(rel < 1 ? 1 : rel);
            float large = logf(rf * (1.0f/80.0f)) * (float)(80.0 / 2.302585092994045684);
            int li = (int)((float)max_exact + large);
            v = li < (nb - 1) ? li : (nb - 1);
        }
        int bucket = rb + v;
        #pragma unroll
        for (int h = 0; h < HH; h++)
            g_bias[idx*HH + h] = rel_embed[bucket*HH + h];
    }
}

// ===========================================================================
// HMMA GEMM, fp16 2-pass (A hi/lo, W fp16), cp.async 3-STAGE, KC=32.
// smem arrays per stage: 0=Ahi, 1=Alo, 2=Whi.
// sel 0/1/2: q/k/v -> fp16 (q scaled).  sel 3: fp32 dense out (A = ctx).
// ===========================================================================
#define KC 32
#define SPITCH 40
#define ARR (128*SPITCH)
#define STG (3*ARR)
#define NSTAGE 3
#define GEMM_SMEM (NSTAGE*STG*2)

__global__ __launch_bounds__(256, 2) void hmma_gemm_kernel(
    const float* __restrict__ b0in, const float* __restrict__ b1in,
    const float* __restrict__ b2in, const float* __restrict__ b3in,
    float* __restrict__ dense_out, int sel_base)
{
    extern __shared__ __half sh[];
    int tid = threadIdx.x;
    int sel = sel_base + blockIdx.z;
    int m0 = blockIdx.y * 128, n0 = blockIdx.x * 128;

    const __half* Ahi = (sel < 3) ? g_xhi : g_chi;
    const __half* Alo = (sel < 3) ? g_xlo : g_clo;
    const __half* Whi = g_whi + ((size_t)sel << 20);
    const float* bias = sel==0 ? b0in : sel==1 ? b1in : sel==2 ? b2in : b3in;

    int wid = tid >> 5, lane = tid & 31;
    int warp_m = wid >> 2, warp_n = wid & 3;
    int gID = lane >> 2, tig = lane & 3;
    uint32_t sb = smem_u32(sh);

    int cp_arr[6], cp_r[6], cp_c8[6];
    #pragma unroll
    for (int j = 0; j < 6; j++) {
        int idx = tid + j*256;
        cp_arr[j] = idx >> 9;
        int c = idx & 511;
        cp_r[j] = c >> 2;
        cp_c8[j] = (c & 3) * 8;
    }

    float acc[4][4][4];
    #pragma unroll
    for (int mf = 0; mf < 4; mf++)
        #pragma unroll
        for (int nf = 0; nf < 4; nf++)
            #pragma unroll
            for (int c = 0; c < 4; c++) acc[mf][nf][c] = 0.0f;

    const int NK = EE / KC;   // 32

    auto prefetch = [&](int kt, int stage) {
        int k0 = kt * KC;
        uint32_t stg = sb + (uint32_t)stage*STG*2;
        #pragma unroll
        for (int j = 0; j < 6; j++) {
            int a = cp_arr[j], r = cp_r[j], c8 = cp_c8[j];
            const __half* src =
                (a == 0) ? (Ahi + (size_t)(m0+r)*EE + k0 + c8) :
                (a == 1) ? (Alo + (size_t)(m0+r)*EE + k0 + c8) :
                           (Whi + (size_t)(n0+r)*EE + k0 + c8);
            cp16(stg + (uint32_t)(a*ARR + r*SPITCH + c8)*2, src);
        }
    };

    prefetch(0, 0); CP_COMMIT();
    prefetch(1, 1); CP_COMMIT();

    int stage = 0;
    for (int kt = 0; kt < NK; kt++) {
        if (kt + 2 < NK) {
            int s2 = (stage + 2) % NSTAGE;
            prefetch(kt + 2, s2);
            CP_COMMIT();
            CP_WAIT2();
        } else if (kt + 1 < NK) {
            CP_WAIT1();
        } else {
            CP_WAIT0();
        }
        __syncthreads();

        const __half* s = sh + stage*STG;
        #pragma unroll
        for (int ks = 0; ks < KC/16; ks++) {
            int kc = ks*16 + 2*tig;
            uint32_t bh[4][2];
            #pragma unroll
            for (int nf = 0; nf < 4; nf++) {
                int n = warp_n*32 + nf*8 + gID;
                bh[nf][0] = *(const uint32_t*)&s[2*ARR + n*SPITCH + kc];
                bh[nf][1] = *(const uint32_t*)&s[2*ARR + n*SPITCH + kc + 8];
            }
            #pragma unroll
            for (int mf = 0; mf < 4; mf++) {
                int r = warp_m*64 + mf*16 + gID;
                uint32_t ah0 = *(const uint32_t*)&s[r*SPITCH + kc];
                uint32_t ah1 = *(const uint32_t*)&s[(r+8)*SPITCH + kc];
                uint32_t ah2 = *(const uint32_t*)&s[r*SPITCH + kc + 8];
                uint32_t ah3 = *(const uint32_t*)&s[(r+8)*SPITCH + kc + 8];
                uint32_t al0 = *(const uint32_t*)&s[ARR + r*SPITCH + kc];
                uint32_t al1 = *(const uint32_t*)&s[ARR + (r+8)*SPITCH + kc];
                uint32_t al2 = *(const uint32_t*)&s[ARR + r*SPITCH + kc + 8];
                uint32_t al3 = *(const uint32_t*)&s[ARR + (r+8)*SPITCH + kc + 8];
                #pragma unroll
                for (int nf = 0; nf < 4; nf++) {
                    hmma16816(acc[mf][nf], ah0, ah1, ah2, ah3, bh[nf][0], bh[nf][1]);
                    hmma16816(acc[mf][nf], al0, al1, al2, al3, bh[nf][0], bh[nf][1]);
                }
            }
        }
        __syncthreads();
        stage = (stage + 1) % NSTAGE;
    }

    float scale = (sel == 0) ? 0.125f : 1.0f;
    #pragma unroll
    for (int mf = 0; mf < 4; mf++) {
        int m = m0 + warp_m*64 + mf*16 + gID;
        #pragma unroll
        for (int nf = 0; nf < 4; nf++) {
            int n = n0 + warp_n*32 + nf*8 + 2*tig;
            float bx = bias[n], by = bias[n+1];
            float v0 = (acc[mf][nf][0] + bx)*scale, v1 = (acc[mf][nf][1] + by)*scale;
            float v2 = (acc[mf][nf][2] + bx)*scale, v3 = (acc[mf][nf][3] + by)*scale;
            if (sel < 3) {
                int h = n >> 6, d = n & 63;
                int b1 = m >> 11, t1 = m & (TT-1);
                int m2 = m + 8;
                int b2 = m2 >> 11, t2 = m2 & (TT-1);
                size_t o1 = (((size_t)(b1*HH + h))*TT + t1)*DD + d;
                size_t o2 = (((size_t)(b2*HH + h))*TT + t2)*DD + d;
                __half* dst = (sel == 0) ? g_qh : (sel == 1) ? g_kh : g_vh;
                *(uint32_t*)&dst[o1] = packh2(v0, v1);
                *(uint32_t*)&dst[o2] = packh2(v2, v3);
            } else {
                *(float2*)&dense_out[(size_t)m*EE + n] = make_float2(v0, v1);
                *(float2*)&dense_out[(size_t)(m+8)*EE + n] = make_float2(v2, v3);
            }
        }
    }
}

// ===========================================================================
// HMMA flash attention: QK 1-pass fp16, PV 1-pass fp16, online-max softmax,
// cp.async 2-stage, KV chunk 64.
// ===========================================================================
#define AT_KP 72
#define AT_TILE (64*AT_KP)
#define AT_STG (2*AT_TILE)
#define ATTN_SMEM (2*AT_STG*2 + 2*192*4)

__global__ __launch_bounds__(256, 2) void attn_mma_kernel()
{
    extern __shared__ __half ash[];
    float* bias_s = (float*)(ash + 2*AT_STG);    // [2][192]

    int tid = threadIdx.x;
    int wid = tid >> 5, lane = tid & 31;
    int gID = lane >> 2, tig = lane & 3;
    int bh = blockIdx.y;
    int b = bh >> 4, h = bh & 15;
    int t0 = blockIdx.x * 128;

    const __half* qh = g_qh + ((size_t)bh*TT + t0)*DD;
    const __half* kh = g_kh + (size_t)bh*TT*DD;
    const __half* vh = g_vh + (size_t)bh*TT*DD;

    uint32_t qah[4][4];
    int qr0 = wid*16 + gID;
    #pragma unroll
    for (int ks = 0; ks < 4; ks++) {
        qah[ks][0] = *(const uint32_t*)&qh[(size_t)qr0*DD + ks*16 + 2*tig];
        qah[ks][1] = *(const uint32_t*)&qh[(size_t)(qr0+8)*DD + ks*16 + 2*tig];
        qah[ks][2] = *(const uint32_t*)&qh[(size_t)qr0*DD + ks*16 + 8 + 2*tig];
        qah[ks][3] = *(const uint32_t*)&qh[(size_t)(qr0+8)*DD + ks*16 + 8 + 2*tig];
    }
    float g0_ = g_gate[(size_t)bh*TT + t0 + wid*16 + gID];
    float g1_ = g_gate[(size_t)bh*TT + t0 + wid*16 + gID + 8];

    float m0 = -1e30f, m1 = -1e30f, l0 = 0.0f, l1 = 0.0f;
    float oa[8][4];
    #pragma unroll
    for (int nf = 0; nf < 8; nf++)
        #pragma unroll
        for (int c = 0; c < 4; c++) oa[nf][c] = 0.0f;

    uint32_t sb = smem_u32(ash);

    auto loadKV = [&](int s0, int stage) {
        uint32_t stg = sb + (uint32_t)stage*AT_STG*2;
        #pragma unroll
        for (int j = 0; j < 4; j++) {
            int idx = tid + j*256;
            int a = idx >> 9;
            int c = idx & 511;
            int r = c >> 3, c8 = (c & 7)*8;
            size_t go = (size_t)(s0+r)*DD + c8;
            const __half* src = (a==0) ? kh+go : vh+go;
            cp16(stg + (uint32_t)(a*AT_TILE + r*AT_KP + c8)*2, src);
        }
    };

    const int NC = TT/64;
    loadKV(0, 0);
    CP_COMMIT();

    for (int ch = 0; ch < NC; ch++) {
        int cur = ch & 1;
        int s0 = ch * 64;
        if (ch + 1 < NC) { loadKV(s0 + 64, cur^1); CP_COMMIT(); CP_WAIT1(); }
        else             { CP_WAIT0(); }
        if (tid < 191)
            bias_s[cur*192 + tid] = g_bias[(size_t)(s0 - t0 - 127 + tid + TT - 1)*HH + h];
        __syncthreads();

        uint32_t kh_b = sb + (uint32_t)(cur*AT_STG)*2;
        uint32_t vh_b = kh_b + AT_TILE*2;
        const float* bw = bias_s + cur*192;

        // ---- S = Q K^T, 1-pass fp16
        float sc[8][4];
        #pragma unroll
        for (int nf = 0; nf < 8; nf++)
            #pragma unroll
            for (int c = 0; c < 4; c++) sc[nf][c] = 0.0f;

        #pragma unroll
        for (int ks = 0; ks < 4; ks++) {
            #pragma unroll
            for (int np = 0; np < 4; np++) {
                uint32_t rowoff = (((np*16 + ((lane>>4)<<3) + (lane&7))*AT_KP) + ks*16 + (((lane>>3)&1)<<3))*2;
                uint32_t rh0, rh1, rh2, rh3;
                asm volatile("ldmatrix.sync.aligned.m8n8.x4.shared.b16 {%0,%1,%2,%3}, [%4];"
                             : "=r"(rh0), "=r"(rh1), "=r"(rh2), "=r"(rh3) : "r"(kh_b + rowoff));
                hmma16816(sc[2*np],   qah[ks][0], qah[ks][1], qah[ks][2], qah[ks][3], rh0, rh1);
                hmma16816(sc[2*np+1], qah[ks][0], qah[ks][1], qah[ks][2], qah[ks][3], rh2, rh3);
            }
        }

        // ---- bias + online-max softmax
        float mx0 = -1e30f, mx1 = -1e30f;
        #pragma unroll
        for (int nf = 0; nf < 8; nf++) {
            int u = nf*8 + 2*tig - (wid*16 + gID) + 127;
            sc[nf][0] = fmaf(g0_, bw[u],   sc[nf][0]);
            sc[nf][1] = fmaf(g0_, bw[u+1], sc[nf][1]);
            sc[nf][2] = fmaf(g1_, bw[u-8], sc[nf][2]);
            sc[nf][3] = fmaf(g1_, bw[u-7], sc[nf][3]);
            mx0 = fmaxf(mx0, fmaxf(sc[nf][0], sc[nf][1]));
            mx1 = fmaxf(mx1, fmaxf(sc[nf][2], sc[nf][3]));
        }
        mx0 = fmaxf(mx0, __shfl_xor_sync(0xffffffffu, mx0, 1));
        mx0 = fmaxf(mx0, __shfl_xor_sync(0xffffffffu, mx0, 2));
        mx1 = fmaxf(mx1, __shfl_xor_sync(0xffffffffu, mx1, 1));
        mx1 = fmaxf(mx1, __shfl_xor_sync(0xffffffffu, mx1, 2));

        float mn0 = fmaxf(m0, mx0), mn1 = fmaxf(m1, mx1);
        float al0 = fexp(m0 - mn0), al1 = fexp(m1 - mn1);
        l0 *= al0;  l1 *= al1;
        #pragma unroll
        for (int nf = 0; nf < 8; nf++) {
            sc[nf][0] = fexp(sc[nf][0] - mn0); l0 += sc[nf][0];
            sc[nf][1] = fexp(sc[nf][1] - mn0); l0 += sc[nf][1];
            sc[nf][2] = fexp(sc[nf][2] - mn1); l1 += sc[nf][2];
            sc[nf][3] = fexp(sc[nf][3] - mn1); l1 += sc[nf][3];
        }
        m0 = mn0;  m1 = mn1;
        #pragma unroll
        for (int nf = 0; nf < 8; nf++) {
            oa[nf][0] *= al0; oa[nf][1] *= al0;
            oa[nf][2] *= al1; oa[nf][3] *= al1;
        }

        // ---- O += P V, 1-pass fp16
        #pragma unroll
        for (int ksp = 0; ksp < 4; ksp++) {
            uint32_t pa0 = packh2(sc[2*ksp][0],   sc[2*ksp][1]);
            uint32_t pa1 = packh2(sc[2*ksp][2],   sc[2*ksp][3]);
            uint32_t pa2 = packh2(sc[2*ksp+1][0], sc[2*ksp+1][1]);
            uint32_t pa3 = packh2(sc[2*ksp+1][2], sc[2*ksp+1][3]);
            #pragma unroll
            for (int np = 0; np < 4; np++) {
                uint32_t rowoff = (((16*ksp + (lane&15))*AT_KP) + np*16 + ((lane>>4)<<3))*2;
                uint32_t rh0, rh1, rh2, rh3;
                asm volatile("ldmatrix.sync.aligned.m8n8.x4.trans.shared.b16 {%0,%1,%2,%3}, [%4];"
                             : "=r"(rh0), "=r"(rh1), "=r"(rh2), "=r"(rh3) : "r"(vh_b + rowoff));
                hmma16816(oa[2*np],   pa0, pa1, pa2, pa3, rh0, rh1);
                hmma16816(oa[2*np+1], pa0, pa1, pa2, pa3, rh2, rh3);
            }
        }
        __syncthreads();
    }

    l0 += __shfl_xor_sync(0xffffffffu, l0, 1);
    l0 += __shfl_xor_sync(0xffffffffu, l0, 2);
    l1 += __shfl_xor_sync(0xffffffffu, l1, 1);
    l1 += __shfl_xor_sync(0xffffffffu, l1, 2);
    float inv0 = 1.0f / l0, inv1 = 1.0f / l1;
    int t = t0 + wid*16 + gID;
    #pragma unroll
    for (int nf = 0; nf < 8; nf++) {
        int d = nf*8 + 2*tig;
        uint32_t h0, l0p, h1, l1p;
        splith2(oa[nf][0]*inv0, oa[nf][1]*inv0, h0, l0p);
        splith2(oa[nf][2]*inv1, oa[nf][3]*inv1, h1, l1p);
        size_t o0 = ((size_t)(b*TT + t))*EE + h*DD + d;
        size_t o1 = ((size_t)(b*TT + t + 8))*EE + h*DD + d;
        *(uint32_t*)&g_chi[o0] = h0;
        *(uint32_t*)&g_chi[o1] = h1;
        *(uint32_t*)&g_clo[o0] = l0p;
        *(uint32_t*)&g_clo[o1] = l1p;
    }
}

// ---------------------------------------------------------------------------
extern "C" void kernel_launch(void* const* d_in, const int* in_sizes, int n_in,
                              void* d_out, int out_size)
{
    const float* hidden    = (const float*)d_in[0];
    const float* q_w       = (const float*)d_in[1];
    const float* q_b       = (const float*)d_in[2];
    const float* k_w       = (const float*)d_in[3];
    const float* k_b       = (const float*)d_in[4];
    const float* v_w       = (const float*)d_in[5];
    const float* v_b       = (const float*)d_in[6];
    const float* out_w     = (const float*)d_in[7];
    const float* out_b     = (const float*)d_in[8];
    const float* rel_embed = (const float*)d_in[9];
    const float* gru_const = (const float*)d_in[10];
    const float* gru_w     = (const float*)d_in[11];
    const float* gru_b     = (const float*)d_in[12];
    float* out = (float*)d_out;

    prep_kernel<<<PREP_BLOCKS, 256>>>(hidden, q_w, k_w, v_w, out_w,
                                      gru_w, gru_b, gru_const, rel_embed);

    cudaFuncSetAttribute(hmma_gemm_kernel, cudaFuncAttributeMaxDynamicSharedMemorySize, GEMM_SMEM);
    hmma_gemm_kernel<<<dim3(EE/128, BT/128, 3), 256, GEMM_SMEM>>>(q_b, k_b, v_b, out_b, out, 0);

    cudaFuncSetAttribute(attn_mma_kernel, cudaFuncAttributeMaxDynamicSharedMemorySize, ATTN_SMEM);
    attn_mma_kernel<<<dim3(TT/128, BB*HH), 256, ATTN_SMEM>>>();

    hmma_gemm_kernel<<<dim3(EE/128, BT/128, 1), 256, GEMM_SMEM>>>(q_b, k_b, v_b, out_b, out, 3);
}